// round 13
// baseline (speedup 1.0000x reference)
#include <cuda_runtime.h>
#include <cuda_bf16.h>
#include <cstdint>
#include <math.h>

#define BATCH 4
#define SEQ 2048
#define DIM 128
#define QH 16
#define KVH 4
#define WINDOW 512

// ---------------------------------------------------------------------------
// device-global scratch (allocation-free)
// ---------------------------------------------------------------------------
__device__ __nv_bfloat16 g_Xh[BATCH * SEQ * DIM];
__device__ __nv_bfloat16 g_Xl[BATCH * SEQ * DIM];
__device__ __nv_bfloat16 g_Wqh[DIM * 3072];
__device__ __nv_bfloat16 g_Wql[DIM * 3072];
__device__ __nv_bfloat16 g_Wph[2048 * DIM];
__device__ __nv_bfloat16 g_Wpl[2048 * DIM];
__device__ __nv_bfloat16 g_Qh[BATCH * QH * SEQ * DIM];
__device__ __nv_bfloat16 g_Ql[BATCH * QH * SEQ * DIM];
__device__ __nv_bfloat16 g_Kh[BATCH * KVH * SEQ * DIM];
__device__ __nv_bfloat16 g_Kl[BATCH * KVH * SEQ * DIM];
__device__ __nv_bfloat16 g_Vh[BATCH * KVH * SEQ * DIM];
__device__ __nv_bfloat16 g_Vl[BATCH * KVH * SEQ * DIM];
__device__ __nv_bfloat16 g_Ah[BATCH * SEQ * QH * DIM];
__device__ __nv_bfloat16 g_Al[BATCH * SEQ * QH * DIM];
__device__ float g_Pp[8 * BATCH * SEQ * DIM];    // proj split-K partials (32MB)

// ---------------------------------------------------------------------------
// base-ISA helpers
// ---------------------------------------------------------------------------
__device__ __forceinline__ uint32_t smem_u32(const void* p) {
    uint32_t a;
    asm("{ .reg .u64 t; cvta.to.shared.u64 t, %1; cvt.u32.u64 %0, t; }" : "=r"(a) : "l"(p));
    return a;
}
__device__ __forceinline__ void ldm_x4(uint32_t* r, uint32_t addr) {
    asm volatile("ldmatrix.sync.aligned.m8n8.x4.shared.b16 {%0,%1,%2,%3},[%4];"
        : "=r"(r[0]), "=r"(r[1]), "=r"(r[2]), "=r"(r[3]) : "r"(addr));
}
__device__ __forceinline__ void ldm_x4t(uint32_t* r, uint32_t addr) {
    asm volatile("ldmatrix.sync.aligned.m8n8.x4.trans.shared.b16 {%0,%1,%2,%3},[%4];"
        : "=r"(r[0]), "=r"(r[1]), "=r"(r[2]), "=r"(r[3]) : "r"(addr));
}
__device__ __forceinline__ void mma_bf16(float* d, const uint32_t* a, const uint32_t* b) {
    asm volatile(
        "mma.sync.aligned.m16n8k16.row.col.f32.bf16.bf16.f32 "
        "{%0,%1,%2,%3},{%4,%5,%6,%7},{%8,%9},{%0,%1,%2,%3};"
        : "+f"(d[0]), "+f"(d[1]), "+f"(d[2]), "+f"(d[3])
        : "r"(a[0]), "r"(a[1]), "r"(a[2]), "r"(a[3]), "r"(b[0]), "r"(b[1]));
}
__device__ __forceinline__ uint32_t pkbf(float lo, float hi) {
    uint32_t r; asm("cvt.rn.bf16x2.f32 %0,%1,%2;" : "=r"(r) : "f"(hi), "f"(lo)); return r;
}
__device__ __forceinline__ float btrunc(float x) {
    return __uint_as_float(__float_as_uint(x) & 0xffff0000u);
}
__device__ __forceinline__ float ex2(float x) {
    float y; asm("ex2.approx.ftz.f32 %0,%1;" : "=f"(y) : "f"(x)); return y;
}
__device__ __forceinline__ void cp16(uint32_t dst, const void* src) {
    asm volatile("cp.async.cg.shared.global [%0], [%1], 16;" :: "r"(dst), "l"(src));
}
__device__ __forceinline__ void cp_commit() { asm volatile("cp.async.commit_group;"); }
template <int N> __device__ __forceinline__ void cp_wait() {
    asm volatile("cp.async.wait_group %0;" :: "n"(N));
}
__device__ __forceinline__ void split2(float v0, float v1, uint32_t& hp, uint32_t& lp) {
    hp = pkbf(v0, v1);
    float h0 = __uint_as_float(hp << 16);
    float h1 = __uint_as_float(hp & 0xffff0000u);
    lp = pkbf(v0 - h0, v1 - h1);
}

// ---------------------------------------------------------------------------
// Kernel 0: split inputs into bf16 hi/lo
// ---------------------------------------------------------------------------
#define NPX (BATCH * SEQ * DIM / 2)
#define NPQ (DIM * 3072 / 2)
#define NPP (2048 * DIM / 2)
__global__ void __launch_bounds__(256) prep_kernel(const float* __restrict__ x,
                                                   const float* __restrict__ Wqkv,
                                                   const float* __restrict__ Wproj) {
    const float qscale = 1.4426950408889634f * 0.08838834764831845f;
    int i = blockIdx.x * 256 + threadIdx.x;
    if (i < NPX) {
        float2 v = *(const float2*)(x + 2 * i);
        uint32_t hp, lp; split2(v.x, v.y, hp, lp);
        *(uint32_t*)(g_Xh + 2 * i) = hp; *(uint32_t*)(g_Xl + 2 * i) = lp;
    } else if (i < NPX + NPQ) {
        int j = i - NPX;
        float2 v = *(const float2*)(Wqkv + 2 * j);
        int col = (2 * j) % 3072;
        if (col < QH * DIM) { v.x *= qscale; v.y *= qscale; }
        uint32_t hp, lp; split2(v.x, v.y, hp, lp);
        *(uint32_t*)(g_Wqh + 2 * j) = hp; *(uint32_t*)(g_Wql + 2 * j) = lp;
    } else if (i < NPX + NPQ + NPP) {
        int j = i - NPX - NPQ;
        float2 v = *(const float2*)(Wproj + 2 * j);
        uint32_t hp, lp; split2(v.x, v.y, hp, lp);
        *(uint32_t*)(g_Wph + 2 * j) = hp; *(uint32_t*)(g_Wpl + 2 * j) = lp;
    }
}

// ---------------------------------------------------------------------------
// Kernel A: qkv via HMMA, 2-phase k-pipelined loads
// ---------------------------------------------------------------------------
#define TSTR_B 272
#define QKV_TILE (128 * TSTR_B)
#define QKV_SMEM (4 * QKV_TILE)

__global__ void __launch_bounds__(256) qkv_kernel() {
    extern __shared__ char smc[];
    const uint32_t sb = smem_u32(smc);
    const int tid = threadIdx.x;
    const int lane = tid & 31;
    const int w = tid >> 5;
    const int m0w = w * 16;
    const int m0 = blockIdx.x * 128;
    const int head = blockIdx.y;
    const int n0 = head * 128;

    for (int idx = tid; idx < 4096; idx += 256) {
        if (idx < 2048) {
            int arr = idx >> 10, r = (idx >> 3) & 127, c = idx & 7;
            const char* src = (const char*)(arr ? g_Xl : g_Xh) + (long)(m0 + r) * 256 + c * 16;
            cp16(sb + arr * QKV_TILE + r * TSTR_B + c * 16, src);
        } else {
            int j = idx - 2048;
            int arr = j >> 10, r = (j >> 4) & 63, c = j & 15;
            const char* src = (const char*)(arr ? g_Wql : g_Wqh) + ((long)r * 3072 + n0) * 2 + c * 16;
            cp16(sb + (2 + arr) * QKV_TILE + r * TSTR_B + c * 16, src);
        }
    }
    cp_commit();
    for (int idx = tid; idx < 4096; idx += 256) {
        if (idx < 2048) {
            int arr = idx >> 10, r = (idx >> 3) & 127, c = (idx & 7) + 8;
            const char* src = (const char*)(arr ? g_Xl : g_Xh) + (long)(m0 + r) * 256 + c * 16;
            cp16(sb + arr * QKV_TILE + r * TSTR_B + c * 16, src);
        } else {
            int j = idx - 2048;
            int arr = j >> 10, r = ((j >> 4) & 63) + 64, c = j & 15;
            const char* src = (const char*)(arr ? g_Wql : g_Wqh) + ((long)r * 3072 + n0) * 2 + c * 16;
            cp16(sb + (2 + arr) * QKV_TILE + r * TSTR_B + c * 16, src);
        }
    }
    cp_commit();

    const uint32_t XH = sb, XL = sb + QKV_TILE;
    const uint32_t WH = sb + 2 * QKV_TILE, WL = sb + 3 * QKV_TILE;
    const uint32_t aoff = (uint32_t)(m0w + (lane & 15)) * TSTR_B + ((lane >> 4) << 3) * 2;
    const uint32_t voff = (uint32_t)((lane & 8) + (lane & 7)) * TSTR_B + ((lane >> 4) << 3) * 2;

    float acc[16][4];
#pragma unroll
    for (int t = 0; t < 16; t++)
#pragma unroll
        for (int j = 0; j < 4; j++) acc[t][j] = 0.0f;

#pragma unroll
    for (int ph = 0; ph < 2; ph++) {
        if (ph == 0) cp_wait<1>(); else cp_wait<0>();
        __syncthreads();
#pragma unroll
        for (int ks2 = 0; ks2 < 4; ks2++) {
            int ks = ph * 4 + ks2;
            uint32_t ah[4], al[4];
            ldm_x4(ah, XH + aoff + ks * 32);
            ldm_x4(al, XL + aoff + ks * 32);
            uint32_t vbase = voff + (uint32_t)(ks * 16) * TSTR_B;
#pragma unroll
            for (int nv = 0; nv < 8; nv++) {
                uint32_t bh[4], bl[4];
                ldm_x4t(bh, WH + vbase + nv * 32);
                ldm_x4t(bl, WL + vbase + nv * 32);
                mma_bf16(acc[2 * nv], ah, bh);
                mma_bf16(acc[2 * nv], ah, bl);
                mma_bf16(acc[2 * nv], al, bh);
                mma_bf16(acc[2 * nv + 1], ah, bh + 2);
                mma_bf16(acc[2 * nv + 1], ah, bl + 2);
                mma_bf16(acc[2 * nv + 1], al, bh + 2);
            }
        }
    }

    __nv_bfloat16 *dh, *dl;
    int hh, nheads;
    if (head < QH)            { dh = g_Qh; dl = g_Ql; hh = head;            nheads = QH; }
    else if (head < QH + KVH) { dh = g_Kh; dl = g_Kl; hh = head - QH;       nheads = KVH; }
    else                      { dh = g_Vh; dl = g_Vl; hh = head - QH - KVH; nheads = KVH; }

    const int mr0 = m0 + m0w + (lane >> 2);
#pragma unroll
    for (int half = 0; half < 2; half++) {
        int m = mr0 + half * 8;
        int b = m >> 11, s = m & 2047;
        long rowo = ((long)(b * nheads + hh) * SEQ + s) * DIM + ((lane & 3) << 1);
#pragma unroll
        for (int t = 0; t < 16; t++) {
            uint32_t hp, lp;
            split2(acc[t][2 * half], acc[t][2 * half + 1], hp, lp);
            *(uint32_t*)(dh + rowo + t * 8) = hp;
            *(uint32_t*)(dl + rowo + t * 8) = lp;
        }
    }
}

// ---------------------------------------------------------------------------
// Kernel B: flash attention (round-12 core) + PV-only kp interval skip
// ---------------------------------------------------------------------------
#define Q_BYTES (128 * TSTR_B)
#define KV_TILE_B (64 * TSTR_B)
#define STAGE_B (4 * KV_TILE_B)
#define ST_OFF (2 * Q_BYTES)
#define ATTN_SMEM (ST_OFF + 2 * STAGE_B)

__global__ void __launch_bounds__(256) attn_kernel() {
    extern __shared__ char smc[];
    const uint32_t sb = smem_u32(smc);
    const int tid = threadIdx.x;
    const int lane = tid & 31;
    const int w = tid >> 5;
    const int m0w = w * 16;

    const int qt = (SEQ / 128 - 1) - blockIdx.x;   // big blocks first
    const int h  = blockIdx.y;
    const int b  = blockIdx.z;
    const int g  = h >> 2;
    const int q0 = qt * 128;
    const float slope2 = exp2f(-(float)(h + 1) * 0.5f) * 1.4426950408889634f;

    const __nv_bfloat16* Qhg = g_Qh + ((long)(b * QH + h) * SEQ + q0) * DIM;
    const __nv_bfloat16* Qlg = g_Ql + ((long)(b * QH + h) * SEQ + q0) * DIM;
    const __nv_bfloat16* Khg = g_Kh + (long)(b * KVH + g) * SEQ * DIM;
    const __nv_bfloat16* Klg = g_Kl + (long)(b * KVH + g) * SEQ * DIM;
    const __nv_bfloat16* Vhg = g_Vh + (long)(b * KVH + g) * SEQ * DIM;
    const __nv_bfloat16* Vlg = g_Vl + (long)(b * KVH + g) * SEQ * DIM;

    const int ktlo = (q0 >= WINDOW) ? (q0 - WINDOW) : 0;
    const int nt = (q0 + 128 - ktlo) >> 6;

    for (int idx = tid; idx < 4096; idx += 256) {
        int arr = idx >> 11, r = (idx >> 4) & 127, c = idx & 15;
        const char* src = (const char*)(arr ? Qlg : Qhg) + r * 256 + c * 16;
        cp16(sb + arr * Q_BYTES + r * TSTR_B + c * 16, src);
    }
    {
        const __nv_bfloat16* srcs[4] = { Khg, Klg, Vhg, Vlg };
        for (int idx = tid; idx < 4096; idx += 256) {
            int arr = idx >> 10, r = (idx >> 4) & 63, c = idx & 15;
            cp16(sb + ST_OFF + arr * KV_TILE_B + r * TSTR_B + c * 16,
                 (const char*)srcs[arr] + (long)(ktlo + r) * 256 + c * 16);
        }
    }
    cp_commit();

    float m0r = -1e30f, m1r = -1e30f, l0 = 0.0f, l1 = 0.0f;
    float oacc[16][4];
#pragma unroll
    for (int t = 0; t < 16; t++)
#pragma unroll
        for (int j = 0; j < 4; j++) oacc[t][j] = 0.0f;

    const int qr0 = q0 + m0w + (lane >> 2);
    const int qr1 = qr0 + 8;
    const int wq_lo = q0 + m0w;
    const int wq_hi = q0 + m0w + 15;

    const uint32_t aoff = (uint32_t)(m0w + (lane & 15)) * TSTR_B + ((lane >> 4) << 3) * 2;
    const uint32_t boff_n = (uint32_t)(((lane >> 4) << 3) + (lane & 7)) * TSTR_B + (lane & 8) * 2;
    const uint32_t voff_r = (uint32_t)((lane & 8) + (lane & 7)) * TSTR_B + ((lane >> 4) << 3) * 2;

    for (int it = 0; it < nt; it++) {
        const int kt = ktlo + it * 64;
        const int st = it & 1;

        if (it + 1 < nt) {
            const int ktn = kt + 64;
            const uint32_t dstb = sb + ST_OFF + (st ^ 1) * STAGE_B;
            const __nv_bfloat16* srcs[4] = { Khg, Klg, Vhg, Vlg };
            for (int idx = tid; idx < 4096; idx += 256) {
                int arr = idx >> 10, r = (idx >> 4) & 63, c = idx & 15;
                cp16(dstb + arr * KV_TILE_B + r * TSTR_B + c * 16,
                     (const char*)srcs[arr] + (long)(ktn + r) * 256 + c * 16);
            }
            cp_commit();
            cp_wait<1>();
        } else {
            cp_wait<0>();
        }
        __syncthreads();

        // warp-level dead-tile skip (exact: all P == 0 for this warp)
        const bool act = (kt <= wq_hi) && (kt + 63 >= wq_lo - WINDOW);
        if (act) {
            const uint32_t kb = sb + ST_OFF + st * STAGE_B;
            const uint32_t KHO = kb, KLO = kb + KV_TILE_B;
            const uint32_t VHO = kb + 2 * KV_TILE_B, VLO = kb + 3 * KV_TILE_B;

            // alive n16 interval (warp-uniform; used for PV skip only)
            const int j_hi = min(3, (wq_hi - kt) >> 4);
            const int dneg = (wq_lo - WINDOW) - kt - 15;
            const int j_lo = (dneg > 0) ? ((dneg + 15) >> 4) : 0;

            float sacc[8][4];
#pragma unroll
            for (int t = 0; t < 8; t++)
#pragma unroll
                for (int j = 0; j < 4; j++) sacc[t][j] = 0.0f;

#pragma unroll
            for (int ks = 0; ks < 8; ks++) {
                uint32_t ah[4], al[4];
                ldm_x4(ah, sb + aoff + ks * 32);
                ldm_x4(al, sb + Q_BYTES + aoff + ks * 32);
#pragma unroll
                for (int ntl = 0; ntl < 4; ntl++) {
                    uint32_t bh[4], bl[4];
                    uint32_t bo = boff_n + (uint32_t)(ntl * 16) * TSTR_B + ks * 32;
                    ldm_x4(bh, KHO + bo);
                    ldm_x4(bl, KLO + bo);
                    mma_bf16(sacc[2 * ntl], ah, bh);
                    mma_bf16(sacc[2 * ntl], ah, bl);
                    mma_bf16(sacc[2 * ntl], al, bh);
                    mma_bf16(sacc[2 * ntl + 1], ah, bh + 2);
                    mma_bf16(sacc[2 * ntl + 1], ah, bl + 2);
                    mma_bf16(sacc[2 * ntl + 1], al, bh + 2);
                }
            }

#pragma unroll
            for (int t = 0; t < 8; t++) {
                int c0 = kt + t * 8 + ((lane & 3) << 1);
                int c1 = c0 + 1;
                int d00 = qr0 - c0, d01 = qr0 - c1, d10 = qr1 - c0, d11 = qr1 - c1;
                sacc[t][0] = (d00 >= 0 && d00 <= WINDOW) ? sacc[t][0] + slope2 * (float)d00 : -1e32f;
                sacc[t][1] = (d01 >= 0 && d01 <= WINDOW) ? sacc[t][1] + slope2 * (float)d01 : -1e32f;
                sacc[t][2] = (d10 >= 0 && d10 <= WINDOW) ? sacc[t][2] + slope2 * (float)d10 : -1e32f;
                sacc[t][3] = (d11 >= 0 && d11 <= WINDOW) ? sacc[t][3] + slope2 * (float)d11 : -1e32f;
            }

            float mx0 = -1e32f, mx1 = -1e32f;
#pragma unroll
            for (int t = 0; t < 8; t++) {
                mx0 = fmaxf(mx0, fmaxf(sacc[t][0], sacc[t][1]));
                mx1 = fmaxf(mx1, fmaxf(sacc[t][2], sacc[t][3]));
            }
            mx0 = fmaxf(mx0, __shfl_xor_sync(0xffffffffu, mx0, 1));
            mx0 = fmaxf(mx0, __shfl_xor_sync(0xffffffffu, mx0, 2));
            mx1 = fmaxf(mx1, __shfl_xor_sync(0xffffffffu, mx1, 1));
            mx1 = fmaxf(mx1, __shfl_xor_sync(0xffffffffu, mx1, 2));
            float mn0 = fmaxf(m0r, mx0), mn1 = fmaxf(m1r, mx1);
            float a0 = ex2(m0r - mn0), a1 = ex2(m1r - mn1);
            m0r = mn0; m1r = mn1;

            float ps0 = 0.0f, ps1 = 0.0f;
#pragma unroll
            for (int t = 0; t < 8; t++) {
                sacc[t][0] = ex2(sacc[t][0] - mn0);
                sacc[t][1] = ex2(sacc[t][1] - mn0);
                sacc[t][2] = ex2(sacc[t][2] - mn1);
                sacc[t][3] = ex2(sacc[t][3] - mn1);
                ps0 += sacc[t][0] + sacc[t][1];
                ps1 += sacc[t][2] + sacc[t][3];
            }
            l0 = l0 * a0 + ps0;
            l1 = l1 * a1 + ps1;
#pragma unroll
            for (int t = 0; t < 16; t++) {
                oacc[t][0] *= a0; oacc[t][1] *= a0;
                oacc[t][2] *= a1; oacc[t][3] *= a1;
            }

            // ---- O += P V with kp alive-interval skip (exact: P==0 outside) ----
#pragma unroll
            for (int kp = 0; kp < 4; kp++) {
                if (kp >= j_lo && kp <= j_hi) {
                    const float* s0 = sacc[2 * kp];
                    const float* s1 = sacc[2 * kp + 1];
                    uint32_t aPh[4], aPl[4];
                    aPh[0] = __byte_perm(__float_as_uint(s0[0]), __float_as_uint(s0[1]), 0x7632);
                    aPh[1] = __byte_perm(__float_as_uint(s0[2]), __float_as_uint(s0[3]), 0x7632);
                    aPh[2] = __byte_perm(__float_as_uint(s1[0]), __float_as_uint(s1[1]), 0x7632);
                    aPh[3] = __byte_perm(__float_as_uint(s1[2]), __float_as_uint(s1[3]), 0x7632);
                    aPl[0] = pkbf(s0[0] - btrunc(s0[0]), s0[1] - btrunc(s0[1]));
                    aPl[1] = pkbf(s0[2] - btrunc(s0[2]), s0[3] - btrunc(s0[3]));
                    aPl[2] = pkbf(s1[0] - btrunc(s1[0]), s1[1] - btrunc(s1[1]));
                    aPl[3] = pkbf(s1[2] - btrunc(s1[2]), s1[3] - btrunc(s1[3]));

                    uint32_t vbase = voff_r + (uint32_t)(kp * 16) * TSTR_B;
#pragma unroll
                    for (int nv = 0; nv < 8; nv++) {
                        uint32_t bvh[4], bvl[4];
                        uint32_t vo = vbase + nv * 32;
                        ldm_x4t(bvh, VHO + vo);
                        ldm_x4t(bvl, VLO + vo);
                        mma_bf16(oacc[2 * nv], aPh, bvh);
                        mma_bf16(oacc[2 * nv], aPh, bvl);
                        mma_bf16(oacc[2 * nv], aPl, bvh);
                        mma_bf16(oacc[2 * nv + 1], aPh, bvh + 2);
                        mma_bf16(oacc[2 * nv + 1], aPh, bvl + 2);
                        mma_bf16(oacc[2 * nv + 1], aPl, bvh + 2);
                    }
                }
            }
        }
        __syncthreads();
    }

    l0 += __shfl_xor_sync(0xffffffffu, l0, 1);
    l0 += __shfl_xor_sync(0xffffffffu, l0, 2);
    l1 += __shfl_xor_sync(0xffffffffu, l1, 1);
    l1 += __shfl_xor_sync(0xffffffffu, l1, 2);
    const float i0 = 1.0f / l0, i1 = 1.0f / l1;

    long r0 = ((long)b * SEQ + qr0) * (QH * DIM) + h * DIM + ((lane & 3) << 1);
    long r1 = ((long)b * SEQ + qr1) * (QH * DIM) + h * DIM + ((lane & 3) << 1);
#pragma unroll
    for (int t = 0; t < 16; t++) {
        uint32_t hp, lp;
        split2(oacc[t][0] * i0, oacc[t][1] * i0, hp, lp);
        *(uint32_t*)(g_Ah + r0 + t * 8) = hp;
        *(uint32_t*)(g_Al + r0 + t * 8) = lp;
        split2(oacc[t][2] * i1, oacc[t][3] * i1, hp, lp);
        *(uint32_t*)(g_Ah + r1 + t * 8) = hp;
        *(uint32_t*)(g_Al + r1 + t * 8) = lp;
    }
}

// ---------------------------------------------------------------------------
// Kernel C: proj split-K=8 partials. Single-buffered, 4 CTAs/SM.
// ---------------------------------------------------------------------------
#define ASTR_B 144
#define PA_TILE (64 * ASTR_B)
#define PW_TILE (64 * TSTR_B)
#define PSTAGE (2 * PA_TILE + 2 * PW_TILE)   // 53248
#define PROJ_SMEM PSTAGE
#define KSPLIT 8

__global__ void __launch_bounds__(128) proj_partial_kernel() {
    extern __shared__ char smc[];
    const uint32_t sb = smem_u32(smc);
    const int tid = threadIdx.x;
    const int lane = tid & 31;
    const int w = tid >> 5;
    const int m0w = w * 16;
    const int m0 = blockIdx.x * 64;
    const int ksplit = blockIdx.y;
    const int kbase = ksplit * (2048 / KSPLIT);

    auto load_chunk = [&](int k0) {
        for (int idx = tid; idx < 3072; idx += 128) {
            if (idx < 1024) {
                int arr = idx >> 9, r = (idx >> 3) & 63, c = idx & 7;
                const char* src = (const char*)(arr ? g_Al : g_Ah) +
                                  (long)(m0 + r) * 4096 + k0 * 2 + c * 16;
                cp16(sb + arr * PA_TILE + r * ASTR_B + c * 16, src);
            } else {
                int j = idx - 1024;
                int arr = j >> 10, r = (j >> 4) & 63, c = j & 15;
                const char* src = (const char*)(arr ? g_Wpl : g_Wph) +
                                  (long)(k0 + r) * 256 + c * 16;
                cp16(sb + 2 * PA_TILE + arr * PW_TILE + r * TSTR_B + c * 16, src);
            }
        }
    };

    const uint32_t aoffA = (uint32_t)(m0w + (lane & 15)) * ASTR_B + ((lane >> 4) << 3) * 2;
    const uint32_t voffW = (uint32_t)((lane & 8) + (lane & 7)) * TSTR_B + ((lane >> 4) << 3) * 2;

    float acc[16][4];
#pragma unroll
    for (int t = 0; t < 16; t++)
#pragma unroll
        for (int j = 0; j < 4; j++) acc[t][j] = 0.0f;

    for (int it = 0; it < 2048 / KSPLIT / 64; it++) {
        load_chunk(kbase + it * 64);
        cp_commit();
        cp_wait<0>();
        __syncthreads();

        const uint32_t AH = sb, AL = sb + PA_TILE;
        const uint32_t WH = sb + 2 * PA_TILE, WL = WH + PW_TILE;

#pragma unroll
        for (int ks = 0; ks < 4; ks++) {
            uint32_t ah[4], al[4];
            ldm_x4(ah, AH + aoffA + ks * 32);
            ldm_x4(al, AL + aoffA + ks * 32);
            uint32_t vbase = voffW + (uint32_t)(ks * 16) * TSTR_B;
#pragma unroll
            for (int nv = 0; nv < 8; nv++) {
                uint32_t bh[4], bl[4];
                ldm_x4t(bh, WH + vbase + nv * 32);
                ldm_x4t(bl, WL + vbase + nv * 32);
                mma_bf16(acc[2 * nv], ah, bh);
                mma_bf16(acc[2 * nv], ah, bl);
                mma_bf16(acc[2 * nv], al, bh);
                mma_bf16(acc[2 * nv + 1], ah, bh + 2);
                mma_bf16(acc[2 * nv + 1], ah, bl + 2);
                mma_bf16(acc[2 * nv + 1], al, bh + 2);
            }
        }
        __syncthreads();
    }

    float* P = g_Pp + (long)ksplit * (BATCH * SEQ * DIM);
    const int mr0 = m0 + m0w + (lane >> 2);
#pragma unroll
    for (int t = 0; t < 16; t++) {
        int col = t * 8 + ((lane & 3) << 1);
        *(float2*)(P + (long)mr0 * 128 + col) = make_float2(acc[t][0], acc[t][1]);
        *(float2*)(P + (long)(mr0 + 8) * 128 + col) = make_float2(acc[t][2], acc[t][3]);
    }
}

// ---------------------------------------------------------------------------
// Kernel D: reduce 8 partials -> out (fixed order, deterministic)
// ---------------------------------------------------------------------------
#define NOUT4 (BATCH * SEQ * DIM / 4)
__global__ void __launch_bounds__(256) proj_reduce_kernel(float* __restrict__ out) {
    int i = blockIdx.x * 256 + threadIdx.x;
    if (i >= NOUT4) return;
    const long stride = (long)BATCH * SEQ * DIM;
    float4 r = *(const float4*)(g_Pp + 4 * (long)i);
#pragma unroll
    for (int s = 1; s < KSPLIT; s++) {
        float4 v = *(const float4*)(g_Pp + s * stride + 4 * (long)i);
        r.x += v.x; r.y += v.y; r.z += v.z; r.w += v.w;
    }
    *(float4*)(out + 4 * (long)i) = r;
}

// ---------------------------------------------------------------------------
extern "C" void kernel_launch(void* const* d_in, const int* in_sizes, int n_in,
                              void* d_out, int out_size) {
    const float* x     = (const float*)d_in[0];
    const float* Wqkv  = (const float*)d_in[1];
    const float* Wproj = (const float*)d_in[2];
    float* out = (float*)d_out;

    prep_kernel<<<(NPX + NPQ + NPP + 255) / 256, 256>>>(x, Wqkv, Wproj);

    cudaFuncSetAttribute(qkv_kernel, cudaFuncAttributeMaxDynamicSharedMemorySize, QKV_SMEM);
    qkv_kernel<<<dim3(8192 / 128, 24), 256, QKV_SMEM>>>();

    cudaFuncSetAttribute(attn_kernel, cudaFuncAttributeMaxDynamicSharedMemorySize, ATTN_SMEM);
    attn_kernel<<<dim3(SEQ / 128, QH, BATCH), 256, ATTN_SMEM>>>();

    cudaFuncSetAttribute(proj_partial_kernel, cudaFuncAttributeMaxDynamicSharedMemorySize, PROJ_SMEM);
    proj_partial_kernel<<<dim3(8192 / 64, KSPLIT), 128, PROJ_SMEM>>>();

    proj_reduce_kernel<<<(NOUT4 + 255) / 256, 256>>>(out);
}

// round 14
// speedup vs baseline: 1.0382x; 1.0382x over previous
#include <cuda_runtime.h>
#include <cuda_bf16.h>
#include <cstdint>
#include <math.h>

#define BATCH 4
#define SEQ 2048
#define DIM 128
#define QH 16
#define KVH 4
#define WINDOW 512

// ---------------------------------------------------------------------------
// device-global scratch (allocation-free)
// ---------------------------------------------------------------------------
__device__ __nv_bfloat16 g_Xh[BATCH * SEQ * DIM];
__device__ __nv_bfloat16 g_Xl[BATCH * SEQ * DIM];
__device__ __nv_bfloat16 g_Wqh[DIM * 3072];
__device__ __nv_bfloat16 g_Wql[DIM * 3072];
__device__ __nv_bfloat16 g_Wph[2048 * DIM];
__device__ __nv_bfloat16 g_Wpl[2048 * DIM];
__device__ __nv_bfloat16 g_Qh[BATCH * QH * SEQ * DIM];
__device__ __nv_bfloat16 g_Ql[BATCH * QH * SEQ * DIM];
__device__ __nv_bfloat16 g_Kh[BATCH * KVH * SEQ * DIM];
__device__ __nv_bfloat16 g_Kl[BATCH * KVH * SEQ * DIM];
__device__ __nv_bfloat16 g_Vh[BATCH * KVH * SEQ * DIM];
__device__ __nv_bfloat16 g_Vl[BATCH * KVH * SEQ * DIM];
__device__ __nv_bfloat16 g_Ah[BATCH * SEQ * QH * DIM];
__device__ __nv_bfloat16 g_Al[BATCH * SEQ * QH * DIM];
__device__ float g_Pp[8 * BATCH * SEQ * DIM];    // proj split-K partials (32MB)

// ---------------------------------------------------------------------------
// base-ISA helpers
// ---------------------------------------------------------------------------
__device__ __forceinline__ uint32_t smem_u32(const void* p) {
    uint32_t a;
    asm("{ .reg .u64 t; cvta.to.shared.u64 t, %1; cvt.u32.u64 %0, t; }" : "=r"(a) : "l"(p));
    return a;
}
__device__ __forceinline__ void ldm_x4(uint32_t* r, uint32_t addr) {
    asm volatile("ldmatrix.sync.aligned.m8n8.x4.shared.b16 {%0,%1,%2,%3},[%4];"
        : "=r"(r[0]), "=r"(r[1]), "=r"(r[2]), "=r"(r[3]) : "r"(addr));
}
__device__ __forceinline__ void ldm_x4t(uint32_t* r, uint32_t addr) {
    asm volatile("ldmatrix.sync.aligned.m8n8.x4.trans.shared.b16 {%0,%1,%2,%3},[%4];"
        : "=r"(r[0]), "=r"(r[1]), "=r"(r[2]), "=r"(r[3]) : "r"(addr));
}
__device__ __forceinline__ void mma_bf16(float* d, const uint32_t* a, const uint32_t* b) {
    asm volatile(
        "mma.sync.aligned.m16n8k16.row.col.f32.bf16.bf16.f32 "
        "{%0,%1,%2,%3},{%4,%5,%6,%7},{%8,%9},{%0,%1,%2,%3};"
        : "+f"(d[0]), "+f"(d[1]), "+f"(d[2]), "+f"(d[3])
        : "r"(a[0]), "r"(a[1]), "r"(a[2]), "r"(a[3]), "r"(b[0]), "r"(b[1]));
}
__device__ __forceinline__ uint32_t pkbf(float lo, float hi) {
    uint32_t r; asm("cvt.rn.bf16x2.f32 %0,%1,%2;" : "=r"(r) : "f"(hi), "f"(lo)); return r;
}
__device__ __forceinline__ float btrunc(float x) {
    return __uint_as_float(__float_as_uint(x) & 0xffff0000u);
}
__device__ __forceinline__ float ex2(float x) {
    float y; asm("ex2.approx.ftz.f32 %0,%1;" : "=f"(y) : "f"(x)); return y;
}
__device__ __forceinline__ void cp16(uint32_t dst, const void* src) {
    asm volatile("cp.async.cg.shared.global [%0], [%1], 16;" :: "r"(dst), "l"(src));
}
__device__ __forceinline__ void cp_commit() { asm volatile("cp.async.commit_group;"); }
template <int N> __device__ __forceinline__ void cp_wait() {
    asm volatile("cp.async.wait_group %0;" :: "n"(N));
}
__device__ __forceinline__ void split2(float v0, float v1, uint32_t& hp, uint32_t& lp) {
    hp = pkbf(v0, v1);
    float h0 = __uint_as_float(hp << 16);
    float h1 = __uint_as_float(hp & 0xffff0000u);
    lp = pkbf(v0 - h0, v1 - h1);
}

// ---------------------------------------------------------------------------
// Kernel 0: split inputs into bf16 hi/lo
// ---------------------------------------------------------------------------
#define NPX (BATCH * SEQ * DIM / 2)
#define NPQ (DIM * 3072 / 2)
#define NPP (2048 * DIM / 2)
__global__ void __launch_bounds__(256) prep_kernel(const float* __restrict__ x,
                                                   const float* __restrict__ Wqkv,
                                                   const float* __restrict__ Wproj) {
    const float qscale = 1.4426950408889634f * 0.08838834764831845f;
    int i = blockIdx.x * 256 + threadIdx.x;
    if (i < NPX) {
        float2 v = *(const float2*)(x + 2 * i);
        uint32_t hp, lp; split2(v.x, v.y, hp, lp);
        *(uint32_t*)(g_Xh + 2 * i) = hp; *(uint32_t*)(g_Xl + 2 * i) = lp;
    } else if (i < NPX + NPQ) {
        int j = i - NPX;
        float2 v = *(const float2*)(Wqkv + 2 * j);
        int col = (2 * j) % 3072;
        if (col < QH * DIM) { v.x *= qscale; v.y *= qscale; }
        uint32_t hp, lp; split2(v.x, v.y, hp, lp);
        *(uint32_t*)(g_Wqh + 2 * j) = hp; *(uint32_t*)(g_Wql + 2 * j) = lp;
    } else if (i < NPX + NPQ + NPP) {
        int j = i - NPX - NPQ;
        float2 v = *(const float2*)(Wproj + 2 * j);
        uint32_t hp, lp; split2(v.x, v.y, hp, lp);
        *(uint32_t*)(g_Wph + 2 * j) = hp; *(uint32_t*)(g_Wpl + 2 * j) = lp;
    }
}

// ---------------------------------------------------------------------------
// Kernel A: qkv via HMMA, 2-phase k-pipelined loads
// ---------------------------------------------------------------------------
#define TSTR_B 272
#define QKV_TILE (128 * TSTR_B)
#define QKV_SMEM (4 * QKV_TILE)

__global__ void __launch_bounds__(256) qkv_kernel() {
    extern __shared__ char smc[];
    const uint32_t sb = smem_u32(smc);
    const int tid = threadIdx.x;
    const int lane = tid & 31;
    const int w = tid >> 5;
    const int m0w = w * 16;
    const int m0 = blockIdx.x * 128;
    const int head = blockIdx.y;
    const int n0 = head * 128;

    for (int idx = tid; idx < 4096; idx += 256) {
        if (idx < 2048) {
            int arr = idx >> 10, r = (idx >> 3) & 127, c = idx & 7;
            const char* src = (const char*)(arr ? g_Xl : g_Xh) + (long)(m0 + r) * 256 + c * 16;
            cp16(sb + arr * QKV_TILE + r * TSTR_B + c * 16, src);
        } else {
            int j = idx - 2048;
            int arr = j >> 10, r = (j >> 4) & 63, c = j & 15;
            const char* src = (const char*)(arr ? g_Wql : g_Wqh) + ((long)r * 3072 + n0) * 2 + c * 16;
            cp16(sb + (2 + arr) * QKV_TILE + r * TSTR_B + c * 16, src);
        }
    }
    cp_commit();
    for (int idx = tid; idx < 4096; idx += 256) {
        if (idx < 2048) {
            int arr = idx >> 10, r = (idx >> 3) & 127, c = (idx & 7) + 8;
            const char* src = (const char*)(arr ? g_Xl : g_Xh) + (long)(m0 + r) * 256 + c * 16;
            cp16(sb + arr * QKV_TILE + r * TSTR_B + c * 16, src);
        } else {
            int j = idx - 2048;
            int arr = j >> 10, r = ((j >> 4) & 63) + 64, c = j & 15;
            const char* src = (const char*)(arr ? g_Wql : g_Wqh) + ((long)r * 3072 + n0) * 2 + c * 16;
            cp16(sb + (2 + arr) * QKV_TILE + r * TSTR_B + c * 16, src);
        }
    }
    cp_commit();

    const uint32_t XH = sb, XL = sb + QKV_TILE;
    const uint32_t WH = sb + 2 * QKV_TILE, WL = sb + 3 * QKV_TILE;
    const uint32_t aoff = (uint32_t)(m0w + (lane & 15)) * TSTR_B + ((lane >> 4) << 3) * 2;
    const uint32_t voff = (uint32_t)((lane & 8) + (lane & 7)) * TSTR_B + ((lane >> 4) << 3) * 2;

    float acc[16][4];
#pragma unroll
    for (int t = 0; t < 16; t++)
#pragma unroll
        for (int j = 0; j < 4; j++) acc[t][j] = 0.0f;

#pragma unroll
    for (int ph = 0; ph < 2; ph++) {
        if (ph == 0) cp_wait<1>(); else cp_wait<0>();
        __syncthreads();
#pragma unroll
        for (int ks2 = 0; ks2 < 4; ks2++) {
            int ks = ph * 4 + ks2;
            uint32_t ah[4], al[4];
            ldm_x4(ah, XH + aoff + ks * 32);
            ldm_x4(al, XL + aoff + ks * 32);
            uint32_t vbase = voff + (uint32_t)(ks * 16) * TSTR_B;
#pragma unroll
            for (int nv = 0; nv < 8; nv++) {
                uint32_t bh[4], bl[4];
                ldm_x4t(bh, WH + vbase + nv * 32);
                ldm_x4t(bl, WL + vbase + nv * 32);
                mma_bf16(acc[2 * nv], ah, bh);
                mma_bf16(acc[2 * nv], ah, bl);
                mma_bf16(acc[2 * nv], al, bh);
                mma_bf16(acc[2 * nv + 1], ah, bh + 2);
                mma_bf16(acc[2 * nv + 1], ah, bl + 2);
                mma_bf16(acc[2 * nv + 1], al, bh + 2);
            }
        }
    }

    __nv_bfloat16 *dh, *dl;
    int hh, nheads;
    if (head < QH)            { dh = g_Qh; dl = g_Ql; hh = head;            nheads = QH; }
    else if (head < QH + KVH) { dh = g_Kh; dl = g_Kl; hh = head - QH;       nheads = KVH; }
    else                      { dh = g_Vh; dl = g_Vl; hh = head - QH - KVH; nheads = KVH; }

    const int mr0 = m0 + m0w + (lane >> 2);
#pragma unroll
    for (int half = 0; half < 2; half++) {
        int m = mr0 + half * 8;
        int b = m >> 11, s = m & 2047;
        long rowo = ((long)(b * nheads + hh) * SEQ + s) * DIM + ((lane & 3) << 1);
#pragma unroll
        for (int t = 0; t < 16; t++) {
            uint32_t hp, lp;
            split2(acc[t][2 * half], acc[t][2 * half + 1], hp, lp);
            *(uint32_t*)(dh + rowo + t * 8) = hp;
            *(uint32_t*)(dl + rowo + t * 8) = lp;
        }
    }
}

// ---------------------------------------------------------------------------
// Kernel B: flash attention (round-12 core) + fully-valid-tile fast path
// ---------------------------------------------------------------------------
#define Q_BYTES (128 * TSTR_B)
#define KV_TILE_B (64 * TSTR_B)
#define STAGE_B (4 * KV_TILE_B)
#define ST_OFF (2 * Q_BYTES)
#define ATTN_SMEM (ST_OFF + 2 * STAGE_B)

__global__ void __launch_bounds__(256) attn_kernel() {
    extern __shared__ char smc[];
    const uint32_t sb = smem_u32(smc);
    const int tid = threadIdx.x;
    const int lane = tid & 31;
    const int w = tid >> 5;
    const int m0w = w * 16;

    const int qt = (SEQ / 128 - 1) - blockIdx.x;   // big blocks first
    const int h  = blockIdx.y;
    const int b  = blockIdx.z;
    const int g  = h >> 2;
    const int q0 = qt * 128;
    const float slope2 = exp2f(-(float)(h + 1) * 0.5f) * 1.4426950408889634f;

    const __nv_bfloat16* Qhg = g_Qh + ((long)(b * QH + h) * SEQ + q0) * DIM;
    const __nv_bfloat16* Qlg = g_Ql + ((long)(b * QH + h) * SEQ + q0) * DIM;
    const __nv_bfloat16* Khg = g_Kh + (long)(b * KVH + g) * SEQ * DIM;
    const __nv_bfloat16* Klg = g_Kl + (long)(b * KVH + g) * SEQ * DIM;
    const __nv_bfloat16* Vhg = g_Vh + (long)(b * KVH + g) * SEQ * DIM;
    const __nv_bfloat16* Vlg = g_Vl + (long)(b * KVH + g) * SEQ * DIM;

    const int ktlo = (q0 >= WINDOW) ? (q0 - WINDOW) : 0;
    const int nt = (q0 + 128 - ktlo) >> 6;

    for (int idx = tid; idx < 4096; idx += 256) {
        int arr = idx >> 11, r = (idx >> 4) & 127, c = idx & 15;
        const char* src = (const char*)(arr ? Qlg : Qhg) + r * 256 + c * 16;
        cp16(sb + arr * Q_BYTES + r * TSTR_B + c * 16, src);
    }
    {
        const __nv_bfloat16* srcs[4] = { Khg, Klg, Vhg, Vlg };
        for (int idx = tid; idx < 4096; idx += 256) {
            int arr = idx >> 10, r = (idx >> 4) & 63, c = idx & 15;
            cp16(sb + ST_OFF + arr * KV_TILE_B + r * TSTR_B + c * 16,
                 (const char*)srcs[arr] + (long)(ktlo + r) * 256 + c * 16);
        }
    }
    cp_commit();

    float m0r = -1e30f, m1r = -1e30f, l0 = 0.0f, l1 = 0.0f;
    float oacc[16][4];
#pragma unroll
    for (int t = 0; t < 16; t++)
#pragma unroll
        for (int j = 0; j < 4; j++) oacc[t][j] = 0.0f;

    const int qr0 = q0 + m0w + (lane >> 2);
    const int qr1 = qr0 + 8;
    const int wq_lo = q0 + m0w;
    const int wq_hi = q0 + m0w + 15;

    const uint32_t aoff = (uint32_t)(m0w + (lane & 15)) * TSTR_B + ((lane >> 4) << 3) * 2;
    const uint32_t boff_n = (uint32_t)(((lane >> 4) << 3) + (lane & 7)) * TSTR_B + (lane & 8) * 2;
    const uint32_t voff_r = (uint32_t)((lane & 8) + (lane & 7)) * TSTR_B + ((lane >> 4) << 3) * 2;

    for (int it = 0; it < nt; it++) {
        const int kt = ktlo + it * 64;
        const int st = it & 1;

        if (it + 1 < nt) {
            const int ktn = kt + 64;
            const uint32_t dstb = sb + ST_OFF + (st ^ 1) * STAGE_B;
            const __nv_bfloat16* srcs[4] = { Khg, Klg, Vhg, Vlg };
            for (int idx = tid; idx < 4096; idx += 256) {
                int arr = idx >> 10, r = (idx >> 4) & 63, c = idx & 15;
                cp16(dstb + arr * KV_TILE_B + r * TSTR_B + c * 16,
                     (const char*)srcs[arr] + (long)(ktn + r) * 256 + c * 16);
            }
            cp_commit();
            cp_wait<1>();
        } else {
            cp_wait<0>();
        }
        __syncthreads();

        // warp-level dead-tile skip (exact: all P == 0 for this warp)
        const bool act = (kt <= wq_hi) && (kt + 63 >= wq_lo - WINDOW);
        if (act) {
            const uint32_t kb = sb + ST_OFF + st * STAGE_B;
            const uint32_t KHO = kb, KLO = kb + KV_TILE_B;
            const uint32_t VHO = kb + 2 * KV_TILE_B, VLO = kb + 3 * KV_TILE_B;

            float sacc[8][4];
#pragma unroll
            for (int t = 0; t < 8; t++)
#pragma unroll
                for (int j = 0; j < 4; j++) sacc[t][j] = 0.0f;

#pragma unroll
            for (int ks = 0; ks < 8; ks++) {
                uint32_t ah[4], al[4];
                ldm_x4(ah, sb + aoff + ks * 32);
                ldm_x4(al, sb + Q_BYTES + aoff + ks * 32);
#pragma unroll
                for (int ntl = 0; ntl < 4; ntl++) {
                    uint32_t bh[4], bl[4];
                    uint32_t bo = boff_n + (uint32_t)(ntl * 16) * TSTR_B + ks * 32;
                    ldm_x4(bh, KHO + bo);
                    ldm_x4(bl, KLO + bo);
                    mma_bf16(sacc[2 * ntl], ah, bh);
                    mma_bf16(sacc[2 * ntl], ah, bl);
                    mma_bf16(sacc[2 * ntl], al, bh);
                    mma_bf16(sacc[2 * ntl + 1], ah, bh + 2);
                    mma_bf16(sacc[2 * ntl + 1], ah, bl + 2);
                    mma_bf16(sacc[2 * ntl + 1], al, bh + 2);
                }
            }

            // ---- ALiBi + mask ----
            // fast path: every (row, col) of this warp-tile is inside the
            // causal window -> masks provably all-true, pure ALiBi adds.
            const bool allvalid = (kt + 63 <= wq_lo) && (kt >= wq_hi - WINDOW);
            if (allvalid) {
                const float f0 = slope2 * (float)(qr0 - kt - ((lane & 3) << 1));
                const float f1 = f0 - slope2;
                const float f2 = f0 + 8.0f * slope2;   // qr1 row
                const float f3 = f2 - slope2;
#pragma unroll
                for (int t = 0; t < 8; t++) {
                    const float dt = (float)(8 * t) * slope2;
                    sacc[t][0] += f0 - dt;
                    sacc[t][1] += f1 - dt;
                    sacc[t][2] += f2 - dt;
                    sacc[t][3] += f3 - dt;
                }
            } else {
#pragma unroll
                for (int t = 0; t < 8; t++) {
                    int c0 = kt + t * 8 + ((lane & 3) << 1);
                    int c1 = c0 + 1;
                    int d00 = qr0 - c0, d01 = qr0 - c1, d10 = qr1 - c0, d11 = qr1 - c1;
                    sacc[t][0] = (d00 >= 0 && d00 <= WINDOW) ? sacc[t][0] + slope2 * (float)d00 : -1e32f;
                    sacc[t][1] = (d01 >= 0 && d01 <= WINDOW) ? sacc[t][1] + slope2 * (float)d01 : -1e32f;
                    sacc[t][2] = (d10 >= 0 && d10 <= WINDOW) ? sacc[t][2] + slope2 * (float)d10 : -1e32f;
                    sacc[t][3] = (d11 >= 0 && d11 <= WINDOW) ? sacc[t][3] + slope2 * (float)d11 : -1e32f;
                }
            }

            float mx0 = -1e32f, mx1 = -1e32f;
#pragma unroll
            for (int t = 0; t < 8; t++) {
                mx0 = fmaxf(mx0, fmaxf(sacc[t][0], sacc[t][1]));
                mx1 = fmaxf(mx1, fmaxf(sacc[t][2], sacc[t][3]));
            }
            mx0 = fmaxf(mx0, __shfl_xor_sync(0xffffffffu, mx0, 1));
            mx0 = fmaxf(mx0, __shfl_xor_sync(0xffffffffu, mx0, 2));
            mx1 = fmaxf(mx1, __shfl_xor_sync(0xffffffffu, mx1, 1));
            mx1 = fmaxf(mx1, __shfl_xor_sync(0xffffffffu, mx1, 2));
            float mn0 = fmaxf(m0r, mx0), mn1 = fmaxf(m1r, mx1);
            float a0 = ex2(m0r - mn0), a1 = ex2(m1r - mn1);
            m0r = mn0; m1r = mn1;

            float ps0 = 0.0f, ps1 = 0.0f;
#pragma unroll
            for (int t = 0; t < 8; t++) {
                sacc[t][0] = ex2(sacc[t][0] - mn0);
                sacc[t][1] = ex2(sacc[t][1] - mn0);
                sacc[t][2] = ex2(sacc[t][2] - mn1);
                sacc[t][3] = ex2(sacc[t][3] - mn1);
                ps0 += sacc[t][0] + sacc[t][1];
                ps1 += sacc[t][2] + sacc[t][3];
            }
            l0 = l0 * a0 + ps0;
            l1 = l1 * a1 + ps1;
#pragma unroll
            for (int t = 0; t < 16; t++) {
                oacc[t][0] *= a0; oacc[t][1] *= a0;
                oacc[t][2] *= a1; oacc[t][3] *= a1;
            }

            // ---- O += P V (unconditional: no per-kp control flow) ----
#pragma unroll
            for (int kp = 0; kp < 4; kp++) {
                const float* s0 = sacc[2 * kp];
                const float* s1 = sacc[2 * kp + 1];
                uint32_t aPh[4], aPl[4];
                aPh[0] = __byte_perm(__float_as_uint(s0[0]), __float_as_uint(s0[1]), 0x7632);
                aPh[1] = __byte_perm(__float_as_uint(s0[2]), __float_as_uint(s0[3]), 0x7632);
                aPh[2] = __byte_perm(__float_as_uint(s1[0]), __float_as_uint(s1[1]), 0x7632);
                aPh[3] = __byte_perm(__float_as_uint(s1[2]), __float_as_uint(s1[3]), 0x7632);
                aPl[0] = pkbf(s0[0] - btrunc(s0[0]), s0[1] - btrunc(s0[1]));
                aPl[1] = pkbf(s0[2] - btrunc(s0[2]), s0[3] - btrunc(s0[3]));
                aPl[2] = pkbf(s1[0] - btrunc(s1[0]), s1[1] - btrunc(s1[1]));
                aPl[3] = pkbf(s1[2] - btrunc(s1[2]), s1[3] - btrunc(s1[3]));

                uint32_t vbase = voff_r + (uint32_t)(kp * 16) * TSTR_B;
#pragma unroll
                for (int nv = 0; nv < 8; nv++) {
                    uint32_t bvh[4], bvl[4];
                    uint32_t vo = vbase + nv * 32;
                    ldm_x4t(bvh, VHO + vo);
                    ldm_x4t(bvl, VLO + vo);
                    mma_bf16(oacc[2 * nv], aPh, bvh);
                    mma_bf16(oacc[2 * nv], aPh, bvl);
                    mma_bf16(oacc[2 * nv], aPl, bvh);
                    mma_bf16(oacc[2 * nv + 1], aPh, bvh + 2);
                    mma_bf16(oacc[2 * nv + 1], aPh, bvl + 2);
                    mma_bf16(oacc[2 * nv + 1], aPl, bvh + 2);
                }
            }
        }
        __syncthreads();
    }

    l0 += __shfl_xor_sync(0xffffffffu, l0, 1);
    l0 += __shfl_xor_sync(0xffffffffu, l0, 2);
    l1 += __shfl_xor_sync(0xffffffffu, l1, 1);
    l1 += __shfl_xor_sync(0xffffffffu, l1, 2);
    const float i0 = 1.0f / l0, i1 = 1.0f / l1;

    long r0 = ((long)b * SEQ + qr0) * (QH * DIM) + h * DIM + ((lane & 3) << 1);
    long r1 = ((long)b * SEQ + qr1) * (QH * DIM) + h * DIM + ((lane & 3) << 1);
#pragma unroll
    for (int t = 0; t < 16; t++) {
        uint32_t hp, lp;
        split2(oacc[t][0] * i0, oacc[t][1] * i0, hp, lp);
        *(uint32_t*)(g_Ah + r0 + t * 8) = hp;
        *(uint32_t*)(g_Al + r0 + t * 8) = lp;
        split2(oacc[t][2] * i1, oacc[t][3] * i1, hp, lp);
        *(uint32_t*)(g_Ah + r1 + t * 8) = hp;
        *(uint32_t*)(g_Al + r1 + t * 8) = lp;
    }
}

// ---------------------------------------------------------------------------
// Kernel C: proj split-K=8 partials. Single-buffered, 4 CTAs/SM.
// ---------------------------------------------------------------------------
#define ASTR_B 144
#define PA_TILE (64 * ASTR_B)
#define PW_TILE (64 * TSTR_B)
#define PSTAGE (2 * PA_TILE + 2 * PW_TILE)   // 53248
#define PROJ_SMEM PSTAGE
#define KSPLIT 8

__global__ void __launch_bounds__(128) proj_partial_kernel() {
    extern __shared__ char smc[];
    const uint32_t sb = smem_u32(smc);
    const int tid = threadIdx.x;
    const int lane = tid & 31;
    const int w = tid >> 5;
    const int m0w = w * 16;
    const int m0 = blockIdx.x * 64;
    const int ksplit = blockIdx.y;
    const int kbase = ksplit * (2048 / KSPLIT);

    auto load_chunk = [&](int k0) {
        for (int idx = tid; idx < 3072; idx += 128) {
            if (idx < 1024) {
                int arr = idx >> 9, r = (idx >> 3) & 63, c = idx & 7;
                const char* src = (const char*)(arr ? g_Al : g_Ah) +
                                  (long)(m0 + r) * 4096 + k0 * 2 + c * 16;
                cp16(sb + arr * PA_TILE + r * ASTR_B + c * 16, src);
            } else {
                int j = idx - 1024;
                int arr = j >> 10, r = (j >> 4) & 63, c = j & 15;
                const char* src = (const char*)(arr ? g_Wpl : g_Wph) +
                                  (long)(k0 + r) * 256 + c * 16;
                cp16(sb + 2 * PA_TILE + arr * PW_TILE + r * TSTR_B + c * 16, src);
            }
        }
    };

    const uint32_t aoffA = (uint32_t)(m0w + (lane & 15)) * ASTR_B + ((lane >> 4) << 3) * 2;
    const uint32_t voffW = (uint32_t)((lane & 8) + (lane & 7)) * TSTR_B + ((lane >> 4) << 3) * 2;

    float acc[16][4];
#pragma unroll
    for (int t = 0; t < 16; t++)
#pragma unroll
        for (int j = 0; j < 4; j++) acc[t][j] = 0.0f;

    for (int it = 0; it < 2048 / KSPLIT / 64; it++) {
        load_chunk(kbase + it * 64);
        cp_commit();
        cp_wait<0>();
        __syncthreads();

        const uint32_t AH = sb, AL = sb + PA_TILE;
        const uint32_t WH = sb + 2 * PA_TILE, WL = WH + PW_TILE;

#pragma unroll
        for (int ks = 0; ks < 4; ks++) {
            uint32_t ah[4], al[4];
            ldm_x4(ah, AH + aoffA + ks * 32);
            ldm_x4(al, AL + aoffA + ks * 32);
            uint32_t vbase = voffW + (uint32_t)(ks * 16) * TSTR_B;
#pragma unroll
            for (int nv = 0; nv < 8; nv++) {
                uint32_t bh[4], bl[4];
                ldm_x4t(bh, WH + vbase + nv * 32);
                ldm_x4t(bl, WL + vbase + nv * 32);
                mma_bf16(acc[2 * nv], ah, bh);
                mma_bf16(acc[2 * nv], ah, bl);
                mma_bf16(acc[2 * nv], al, bh);
                mma_bf16(acc[2 * nv + 1], ah, bh + 2);
                mma_bf16(acc[2 * nv + 1], ah, bl + 2);
                mma_bf16(acc[2 * nv + 1], al, bh + 2);
            }
        }
        __syncthreads();
    }

    float* P = g_Pp + (long)ksplit * (BATCH * SEQ * DIM);
    const int mr0 = m0 + m0w + (lane >> 2);
#pragma unroll
    for (int t = 0; t < 16; t++) {
        int col = t * 8 + ((lane & 3) << 1);
        *(float2*)(P + (long)mr0 * 128 + col) = make_float2(acc[t][0], acc[t][1]);
        *(float2*)(P + (long)(mr0 + 8) * 128 + col) = make_float2(acc[t][2], acc[t][3]);
    }
}

// ---------------------------------------------------------------------------
// Kernel D: reduce 8 partials -> out (fixed order, deterministic)
// ---------------------------------------------------------------------------
#define NOUT4 (BATCH * SEQ * DIM / 4)
__global__ void __launch_bounds__(256) proj_reduce_kernel(float* __restrict__ out) {
    int i = blockIdx.x * 256 + threadIdx.x;
    if (i >= NOUT4) return;
    const long stride = (long)BATCH * SEQ * DIM;
    float4 r = *(const float4*)(g_Pp + 4 * (long)i);
#pragma unroll
    for (int s = 1; s < KSPLIT; s++) {
        float4 v = *(const float4*)(g_Pp + s * stride + 4 * (long)i);
        r.x += v.x; r.y += v.y; r.z += v.z; r.w += v.w;
    }
    *(float4*)(out + 4 * (long)i) = r;
}

// ---------------------------------------------------------------------------
extern "C" void kernel_launch(void* const* d_in, const int* in_sizes, int n_in,
                              void* d_out, int out_size) {
    const float* x     = (const float*)d_in[0];
    const float* Wqkv  = (const float*)d_in[1];
    const float* Wproj = (const float*)d_in[2];
    float* out = (float*)d_out;

    prep_kernel<<<(NPX + NPQ + NPP + 255) / 256, 256>>>(x, Wqkv, Wproj);

    cudaFuncSetAttribute(qkv_kernel, cudaFuncAttributeMaxDynamicSharedMemorySize, QKV_SMEM);
    qkv_kernel<<<dim3(8192 / 128, 24), 256, QKV_SMEM>>>();

    cudaFuncSetAttribute(attn_kernel, cudaFuncAttributeMaxDynamicSharedMemorySize, ATTN_SMEM);
    attn_kernel<<<dim3(SEQ / 128, QH, BATCH), 256, ATTN_SMEM>>>();

    cudaFuncSetAttribute(proj_partial_kernel, cudaFuncAttributeMaxDynamicSharedMemorySize, PROJ_SMEM);
    proj_partial_kernel<<<dim3(8192 / 64, KSPLIT), 128, PROJ_SMEM>>>();

    proj_reduce_kernel<<<(NOUT4 + 255) / 256, 256>>>(out);
}

// round 15
// speedup vs baseline: 1.0527x; 1.0140x over previous
#include <cuda_runtime.h>
#include <cuda_bf16.h>
#include <cstdint>
#include <math.h>

#define BATCH 4
#define SEQ 2048
#define DIM 128
#define QH 16
#define KVH 4
#define WINDOW 512

// ---------------------------------------------------------------------------
// device-global scratch (allocation-free)
// ---------------------------------------------------------------------------
__device__ __nv_bfloat16 g_Xh[BATCH * SEQ * DIM];
__device__ __nv_bfloat16 g_Xl[BATCH * SEQ * DIM];
__device__ __nv_bfloat16 g_Wqh[DIM * 3072];
__device__ __nv_bfloat16 g_Wql[DIM * 3072];
__device__ __nv_bfloat16 g_Wph[2048 * DIM];
__device__ __nv_bfloat16 g_Wpl[2048 * DIM];
__device__ __nv_bfloat16 g_Qh[BATCH * QH * SEQ * DIM];
__device__ __nv_bfloat16 g_Ql[BATCH * QH * SEQ * DIM];
__device__ __nv_bfloat16 g_Kh[BATCH * KVH * SEQ * DIM];
__device__ __nv_bfloat16 g_Kl[BATCH * KVH * SEQ * DIM];
__device__ __nv_bfloat16 g_Vh[BATCH * KVH * SEQ * DIM];
__device__ __nv_bfloat16 g_Vl[BATCH * KVH * SEQ * DIM];
__device__ __nv_bfloat16 g_Ah[BATCH * SEQ * QH * DIM];
__device__ __nv_bfloat16 g_Al[BATCH * SEQ * QH * DIM];
__device__ float g_Pp[8 * BATCH * SEQ * DIM];    // proj split-K partials (32MB)

// ---------------------------------------------------------------------------
// base-ISA helpers
// ---------------------------------------------------------------------------
__device__ __forceinline__ uint32_t smem_u32(const void* p) {
    uint32_t a;
    asm("{ .reg .u64 t; cvta.to.shared.u64 t, %1; cvt.u32.u64 %0, t; }" : "=r"(a) : "l"(p));
    return a;
}
__device__ __forceinline__ void ldm_x4(uint32_t* r, uint32_t addr) {
    asm volatile("ldmatrix.sync.aligned.m8n8.x4.shared.b16 {%0,%1,%2,%3},[%4];"
        : "=r"(r[0]), "=r"(r[1]), "=r"(r[2]), "=r"(r[3]) : "r"(addr));
}
__device__ __forceinline__ void ldm_x4t(uint32_t* r, uint32_t addr) {
    asm volatile("ldmatrix.sync.aligned.m8n8.x4.trans.shared.b16 {%0,%1,%2,%3},[%4];"
        : "=r"(r[0]), "=r"(r[1]), "=r"(r[2]), "=r"(r[3]) : "r"(addr));
}
__device__ __forceinline__ void mma_bf16(float* d, const uint32_t* a, const uint32_t* b) {
    asm volatile(
        "mma.sync.aligned.m16n8k16.row.col.f32.bf16.bf16.f32 "
        "{%0,%1,%2,%3},{%4,%5,%6,%7},{%8,%9},{%0,%1,%2,%3};"
        : "+f"(d[0]), "+f"(d[1]), "+f"(d[2]), "+f"(d[3])
        : "r"(a[0]), "r"(a[1]), "r"(a[2]), "r"(a[3]), "r"(b[0]), "r"(b[1]));
}
__device__ __forceinline__ uint32_t pkbf(float lo, float hi) {
    uint32_t r; asm("cvt.rn.bf16x2.f32 %0,%1,%2;" : "=r"(r) : "f"(hi), "f"(lo)); return r;
}
__device__ __forceinline__ float btrunc(float x) {
    return __uint_as_float(__float_as_uint(x) & 0xffff0000u);
}
__device__ __forceinline__ float ex2(float x) {
    float y; asm("ex2.approx.ftz.f32 %0,%1;" : "=f"(y) : "f"(x)); return y;
}
__device__ __forceinline__ void cp16(uint32_t dst, const void* src) {
    asm volatile("cp.async.cg.shared.global [%0], [%1], 16;" :: "r"(dst), "l"(src));
}
__device__ __forceinline__ void cp_commit() { asm volatile("cp.async.commit_group;"); }
template <int N> __device__ __forceinline__ void cp_wait() {
    asm volatile("cp.async.wait_group %0;" :: "n"(N));
}
__device__ __forceinline__ void split2(float v0, float v1, uint32_t& hp, uint32_t& lp) {
    hp = pkbf(v0, v1);
    float h0 = __uint_as_float(hp << 16);
    float h1 = __uint_as_float(hp & 0xffff0000u);
    lp = pkbf(v0 - h0, v1 - h1);
}

// ---------------------------------------------------------------------------
// Kernel 0: split inputs into bf16 hi/lo
// ---------------------------------------------------------------------------
#define NPX (BATCH * SEQ * DIM / 2)
#define NPQ (DIM * 3072 / 2)
#define NPP (2048 * DIM / 2)
__global__ void __launch_bounds__(256) prep_kernel(const float* __restrict__ x,
                                                   const float* __restrict__ Wqkv,
                                                   const float* __restrict__ Wproj) {
    const float qscale = 1.4426950408889634f * 0.08838834764831845f;
    int i = blockIdx.x * 256 + threadIdx.x;
    if (i < NPX) {
        float2 v = *(const float2*)(x + 2 * i);
        uint32_t hp, lp; split2(v.x, v.y, hp, lp);
        *(uint32_t*)(g_Xh + 2 * i) = hp; *(uint32_t*)(g_Xl + 2 * i) = lp;
    } else if (i < NPX + NPQ) {
        int j = i - NPX;
        float2 v = *(const float2*)(Wqkv + 2 * j);
        int col = (2 * j) % 3072;
        if (col < QH * DIM) { v.x *= qscale; v.y *= qscale; }
        uint32_t hp, lp; split2(v.x, v.y, hp, lp);
        *(uint32_t*)(g_Wqh + 2 * j) = hp; *(uint32_t*)(g_Wql + 2 * j) = lp;
    } else if (i < NPX + NPQ + NPP) {
        int j = i - NPX - NPQ;
        float2 v = *(const float2*)(Wproj + 2 * j);
        uint32_t hp, lp; split2(v.x, v.y, hp, lp);
        *(uint32_t*)(g_Wph + 2 * j) = hp; *(uint32_t*)(g_Wpl + 2 * j) = lp;
    }
}

// ---------------------------------------------------------------------------
// Kernel A: qkv via HMMA. Block 64m x 128n (one head), 128 threads,
// single-buffered (104KB smem -> 2 CTAs/SM). Proj-style warp layout.
// ---------------------------------------------------------------------------
#define TSTR_B 272
#define XA_TILE (64 * TSTR_B)    // 17408
#define WB_TILE (128 * TSTR_B)   // 34816
#define QKV_SMEM (2 * XA_TILE + 2 * WB_TILE)   // 104448

__global__ void __launch_bounds__(128) qkv_kernel() {
    extern __shared__ char smc[];
    const uint32_t sb = smem_u32(smc);
    const int tid = threadIdx.x;
    const int lane = tid & 31;
    const int w = tid >> 5;
    const int m0w = w * 16;
    const int m0 = blockIdx.x * 64;
    const int head = blockIdx.y;         // 0..23
    const int n0 = head * 128;

    // loads: X (2 arrays x 64 rows x 16 chunks) + W (2 arrays x 128 rows x 16 chunks)
    for (int idx = tid; idx < 6144; idx += 128) {
        if (idx < 2048) {
            int arr = idx >> 10, r = (idx >> 4) & 63, c = idx & 15;
            const char* src = (const char*)(arr ? g_Xl : g_Xh) + (long)(m0 + r) * 256 + c * 16;
            cp16(sb + arr * XA_TILE + r * TSTR_B + c * 16, src);
        } else {
            int j = idx - 2048;
            int arr = j >> 11, r = (j >> 4) & 127, c = j & 15;
            const char* src = (const char*)(arr ? g_Wql : g_Wqh) + ((long)r * 3072 + n0) * 2 + c * 16;
            cp16(sb + 2 * XA_TILE + arr * WB_TILE + r * TSTR_B + c * 16, src);
        }
    }
    cp_commit();
    cp_wait<0>();
    __syncthreads();

    const uint32_t XH = sb, XL = sb + XA_TILE;
    const uint32_t WH = sb + 2 * XA_TILE, WL = WH + WB_TILE;
    const uint32_t aoff = (uint32_t)(m0w + (lane & 15)) * TSTR_B + ((lane >> 4) << 3) * 2;
    const uint32_t voff = (uint32_t)((lane & 8) + (lane & 7)) * TSTR_B + ((lane >> 4) << 3) * 2;

    float acc[16][4];
#pragma unroll
    for (int t = 0; t < 16; t++)
#pragma unroll
        for (int j = 0; j < 4; j++) acc[t][j] = 0.0f;

#pragma unroll
    for (int ks = 0; ks < 8; ks++) {
        uint32_t ah[4], al[4];
        ldm_x4(ah, XH + aoff + ks * 32);
        ldm_x4(al, XL + aoff + ks * 32);
        uint32_t vbase = voff + (uint32_t)(ks * 16) * TSTR_B;
#pragma unroll
        for (int nv = 0; nv < 8; nv++) {
            uint32_t bh[4], bl[4];
            ldm_x4t(bh, WH + vbase + nv * 32);
            ldm_x4t(bl, WL + vbase + nv * 32);
            mma_bf16(acc[2 * nv], ah, bh);
            mma_bf16(acc[2 * nv], ah, bl);
            mma_bf16(acc[2 * nv], al, bh);
            mma_bf16(acc[2 * nv + 1], ah, bh + 2);
            mma_bf16(acc[2 * nv + 1], ah, bl + 2);
            mma_bf16(acc[2 * nv + 1], al, bh + 2);
        }
    }

    __nv_bfloat16 *dh, *dl;
    int hh, nheads;
    if (head < QH)            { dh = g_Qh; dl = g_Ql; hh = head;            nheads = QH; }
    else if (head < QH + KVH) { dh = g_Kh; dl = g_Kl; hh = head - QH;       nheads = KVH; }
    else                      { dh = g_Vh; dl = g_Vl; hh = head - QH - KVH; nheads = KVH; }

    const int mr0 = m0 + m0w + (lane >> 2);
#pragma unroll
    for (int half = 0; half < 2; half++) {
        int m = mr0 + half * 8;
        int b = m >> 11, s = m & 2047;
        long rowo = ((long)(b * nheads + hh) * SEQ + s) * DIM + ((lane & 3) << 1);
#pragma unroll
        for (int t = 0; t < 16; t++) {
            uint32_t hp, lp;
            split2(acc[t][2 * half], acc[t][2 * half + 1], hp, lp);
            *(uint32_t*)(dh + rowo + t * 8) = hp;
            *(uint32_t*)(dl + rowo + t * 8) = lp;
        }
    }
}

// ---------------------------------------------------------------------------
// Kernel B: flash attention (round-14 verbatim: dead-tile skip, reversed qt,
// double-buffered cp.async KV, fully-valid-tile ALiBi fast path)
// ---------------------------------------------------------------------------
#define Q_BYTES (128 * TSTR_B)
#define KV_TILE_B (64 * TSTR_B)
#define STAGE_B (4 * KV_TILE_B)
#define ST_OFF (2 * Q_BYTES)
#define ATTN_SMEM (ST_OFF + 2 * STAGE_B)

__global__ void __launch_bounds__(256) attn_kernel() {
    extern __shared__ char smc[];
    const uint32_t sb = smem_u32(smc);
    const int tid = threadIdx.x;
    const int lane = tid & 31;
    const int w = tid >> 5;
    const int m0w = w * 16;

    const int qt = (SEQ / 128 - 1) - blockIdx.x;   // big blocks first
    const int h  = blockIdx.y;
    const int b  = blockIdx.z;
    const int g  = h >> 2;
    const int q0 = qt * 128;
    const float slope2 = exp2f(-(float)(h + 1) * 0.5f) * 1.4426950408889634f;

    const __nv_bfloat16* Qhg = g_Qh + ((long)(b * QH + h) * SEQ + q0) * DIM;
    const __nv_bfloat16* Qlg = g_Ql + ((long)(b * QH + h) * SEQ + q0) * DIM;
    const __nv_bfloat16* Khg = g_Kh + (long)(b * KVH + g) * SEQ * DIM;
    const __nv_bfloat16* Klg = g_Kl + (long)(b * KVH + g) * SEQ * DIM;
    const __nv_bfloat16* Vhg = g_Vh + (long)(b * KVH + g) * SEQ * DIM;
    const __nv_bfloat16* Vlg = g_Vl + (long)(b * KVH + g) * SEQ * DIM;

    const int ktlo = (q0 >= WINDOW) ? (q0 - WINDOW) : 0;
    const int nt = (q0 + 128 - ktlo) >> 6;

    for (int idx = tid; idx < 4096; idx += 256) {
        int arr = idx >> 11, r = (idx >> 4) & 127, c = idx & 15;
        const char* src = (const char*)(arr ? Qlg : Qhg) + r * 256 + c * 16;
        cp16(sb + arr * Q_BYTES + r * TSTR_B + c * 16, src);
    }
    {
        const __nv_bfloat16* srcs[4] = { Khg, Klg, Vhg, Vlg };
        for (int idx = tid; idx < 4096; idx += 256) {
            int arr = idx >> 10, r = (idx >> 4) & 63, c = idx & 15;
            cp16(sb + ST_OFF + arr * KV_TILE_B + r * TSTR_B + c * 16,
                 (const char*)srcs[arr] + (long)(ktlo + r) * 256 + c * 16);
        }
    }
    cp_commit();

    float m0r = -1e30f, m1r = -1e30f, l0 = 0.0f, l1 = 0.0f;
    float oacc[16][4];
#pragma unroll
    for (int t = 0; t < 16; t++)
#pragma unroll
        for (int j = 0; j < 4; j++) oacc[t][j] = 0.0f;

    const int qr0 = q0 + m0w + (lane >> 2);
    const int qr1 = qr0 + 8;
    const int wq_lo = q0 + m0w;
    const int wq_hi = q0 + m0w + 15;

    const uint32_t aoff = (uint32_t)(m0w + (lane & 15)) * TSTR_B + ((lane >> 4) << 3) * 2;
    const uint32_t boff_n = (uint32_t)(((lane >> 4) << 3) + (lane & 7)) * TSTR_B + (lane & 8) * 2;
    const uint32_t voff_r = (uint32_t)((lane & 8) + (lane & 7)) * TSTR_B + ((lane >> 4) << 3) * 2;

    for (int it = 0; it < nt; it++) {
        const int kt = ktlo + it * 64;
        const int st = it & 1;

        if (it + 1 < nt) {
            const int ktn = kt + 64;
            const uint32_t dstb = sb + ST_OFF + (st ^ 1) * STAGE_B;
            const __nv_bfloat16* srcs[4] = { Khg, Klg, Vhg, Vlg };
            for (int idx = tid; idx < 4096; idx += 256) {
                int arr = idx >> 10, r = (idx >> 4) & 63, c = idx & 15;
                cp16(dstb + arr * KV_TILE_B + r * TSTR_B + c * 16,
                     (const char*)srcs[arr] + (long)(ktn + r) * 256 + c * 16);
            }
            cp_commit();
            cp_wait<1>();
        } else {
            cp_wait<0>();
        }
        __syncthreads();

        // warp-level dead-tile skip (exact: all P == 0 for this warp)
        const bool act = (kt <= wq_hi) && (kt + 63 >= wq_lo - WINDOW);
        if (act) {
            const uint32_t kb = sb + ST_OFF + st * STAGE_B;
            const uint32_t KHO = kb, KLO = kb + KV_TILE_B;
            const uint32_t VHO = kb + 2 * KV_TILE_B, VLO = kb + 3 * KV_TILE_B;

            float sacc[8][4];
#pragma unroll
            for (int t = 0; t < 8; t++)
#pragma unroll
                for (int j = 0; j < 4; j++) sacc[t][j] = 0.0f;

#pragma unroll
            for (int ks = 0; ks < 8; ks++) {
                uint32_t ah[4], al[4];
                ldm_x4(ah, sb + aoff + ks * 32);
                ldm_x4(al, sb + Q_BYTES + aoff + ks * 32);
#pragma unroll
                for (int ntl = 0; ntl < 4; ntl++) {
                    uint32_t bh[4], bl[4];
                    uint32_t bo = boff_n + (uint32_t)(ntl * 16) * TSTR_B + ks * 32;
                    ldm_x4(bh, KHO + bo);
                    ldm_x4(bl, KLO + bo);
                    mma_bf16(sacc[2 * ntl], ah, bh);
                    mma_bf16(sacc[2 * ntl], ah, bl);
                    mma_bf16(sacc[2 * ntl], al, bh);
                    mma_bf16(sacc[2 * ntl + 1], ah, bh + 2);
                    mma_bf16(sacc[2 * ntl + 1], ah, bl + 2);
                    mma_bf16(sacc[2 * ntl + 1], al, bh + 2);
                }
            }

            // ---- ALiBi + mask (fast path for fully-valid tiles) ----
            const bool allvalid = (kt + 63 <= wq_lo) && (kt >= wq_hi - WINDOW);
            if (allvalid) {
                const float f0 = slope2 * (float)(qr0 - kt - ((lane & 3) << 1));
                const float f1 = f0 - slope2;
                const float f2 = f0 + 8.0f * slope2;
                const float f3 = f2 - slope2;
#pragma unroll
                for (int t = 0; t < 8; t++) {
                    const float dt = (float)(8 * t) * slope2;
                    sacc[t][0] += f0 - dt;
                    sacc[t][1] += f1 - dt;
                    sacc[t][2] += f2 - dt;
                    sacc[t][3] += f3 - dt;
                }
            } else {
#pragma unroll
                for (int t = 0; t < 8; t++) {
                    int c0 = kt + t * 8 + ((lane & 3) << 1);
                    int c1 = c0 + 1;
                    int d00 = qr0 - c0, d01 = qr0 - c1, d10 = qr1 - c0, d11 = qr1 - c1;
                    sacc[t][0] = (d00 >= 0 && d00 <= WINDOW) ? sacc[t][0] + slope2 * (float)d00 : -1e32f;
                    sacc[t][1] = (d01 >= 0 && d01 <= WINDOW) ? sacc[t][1] + slope2 * (float)d01 : -1e32f;
                    sacc[t][2] = (d10 >= 0 && d10 <= WINDOW) ? sacc[t][2] + slope2 * (float)d10 : -1e32f;
                    sacc[t][3] = (d11 >= 0 && d11 <= WINDOW) ? sacc[t][3] + slope2 * (float)d11 : -1e32f;
                }
            }

            float mx0 = -1e32f, mx1 = -1e32f;
#pragma unroll
            for (int t = 0; t < 8; t++) {
                mx0 = fmaxf(mx0, fmaxf(sacc[t][0], sacc[t][1]));
                mx1 = fmaxf(mx1, fmaxf(sacc[t][2], sacc[t][3]));
            }
            mx0 = fmaxf(mx0, __shfl_xor_sync(0xffffffffu, mx0, 1));
            mx0 = fmaxf(mx0, __shfl_xor_sync(0xffffffffu, mx0, 2));
            mx1 = fmaxf(mx1, __shfl_xor_sync(0xffffffffu, mx1, 1));
            mx1 = fmaxf(mx1, __shfl_xor_sync(0xffffffffu, mx1, 2));
            float mn0 = fmaxf(m0r, mx0), mn1 = fmaxf(m1r, mx1);
            float a0 = ex2(m0r - mn0), a1 = ex2(m1r - mn1);
            m0r = mn0; m1r = mn1;

            float ps0 = 0.0f, ps1 = 0.0f;
#pragma unroll
            for (int t = 0; t < 8; t++) {
                sacc[t][0] = ex2(sacc[t][0] - mn0);
                sacc[t][1] = ex2(sacc[t][1] - mn0);
                sacc[t][2] = ex2(sacc[t][2] - mn1);
                sacc[t][3] = ex2(sacc[t][3] - mn1);
                ps0 += sacc[t][0] + sacc[t][1];
                ps1 += sacc[t][2] + sacc[t][3];
            }
            l0 = l0 * a0 + ps0;
            l1 = l1 * a1 + ps1;
#pragma unroll
            for (int t = 0; t < 16; t++) {
                oacc[t][0] *= a0; oacc[t][1] *= a0;
                oacc[t][2] *= a1; oacc[t][3] *= a1;
            }

            // ---- O += P V (unconditional: no per-kp control flow) ----
#pragma unroll
            for (int kp = 0; kp < 4; kp++) {
                const float* s0 = sacc[2 * kp];
                const float* s1 = sacc[2 * kp + 1];
                uint32_t aPh[4], aPl[4];
                aPh[0] = __byte_perm(__float_as_uint(s0[0]), __float_as_uint(s0[1]), 0x7632);
                aPh[1] = __byte_perm(__float_as_uint(s0[2]), __float_as_uint(s0[3]), 0x7632);
                aPh[2] = __byte_perm(__float_as_uint(s1[0]), __float_as_uint(s1[1]), 0x7632);
                aPh[3] = __byte_perm(__float_as_uint(s1[2]), __float_as_uint(s1[3]), 0x7632);
                aPl[0] = pkbf(s0[0] - btrunc(s0[0]), s0[1] - btrunc(s0[1]));
                aPl[1] = pkbf(s0[2] - btrunc(s0[2]), s0[3] - btrunc(s0[3]));
                aPl[2] = pkbf(s1[0] - btrunc(s1[0]), s1[1] - btrunc(s1[1]));
                aPl[3] = pkbf(s1[2] - btrunc(s1[2]), s1[3] - btrunc(s1[3]));

                uint32_t vbase = voff_r + (uint32_t)(kp * 16) * TSTR_B;
#pragma unroll
                for (int nv = 0; nv < 8; nv++) {
                    uint32_t bvh[4], bvl[4];
                    uint32_t vo = vbase + nv * 32;
                    ldm_x4t(bvh, VHO + vo);
                    ldm_x4t(bvl, VLO + vo);
                    mma_bf16(oacc[2 * nv], aPh, bvh);
                    mma_bf16(oacc[2 * nv], aPh, bvl);
                    mma_bf16(oacc[2 * nv], aPl, bvh);
                    mma_bf16(oacc[2 * nv + 1], aPh, bvh + 2);
                    mma_bf16(oacc[2 * nv + 1], aPh, bvl + 2);
                    mma_bf16(oacc[2 * nv + 1], aPl, bvh + 2);
                }
            }
        }
        __syncthreads();
    }

    l0 += __shfl_xor_sync(0xffffffffu, l0, 1);
    l0 += __shfl_xor_sync(0xffffffffu, l0, 2);
    l1 += __shfl_xor_sync(0xffffffffu, l1, 1);
    l1 += __shfl_xor_sync(0xffffffffu, l1, 2);
    const float i0 = 1.0f / l0, i1 = 1.0f / l1;

    long r0 = ((long)b * SEQ + qr0) * (QH * DIM) + h * DIM + ((lane & 3) << 1);
    long r1 = ((long)b * SEQ + qr1) * (QH * DIM) + h * DIM + ((lane & 3) << 1);
#pragma unroll
    for (int t = 0; t < 16; t++) {
        uint32_t hp, lp;
        split2(oacc[t][0] * i0, oacc[t][1] * i0, hp, lp);
        *(uint32_t*)(g_Ah + r0 + t * 8) = hp;
        *(uint32_t*)(g_Al + r0 + t * 8) = lp;
        split2(oacc[t][2] * i1, oacc[t][3] * i1, hp, lp);
        *(uint32_t*)(g_Ah + r1 + t * 8) = hp;
        *(uint32_t*)(g_Al + r1 + t * 8) = lp;
    }
}

// ---------------------------------------------------------------------------
// Kernel C: proj split-K=8 partials. Single-buffered, 4 CTAs/SM.
// ---------------------------------------------------------------------------
#define ASTR_B 144
#define PA_TILE (64 * ASTR_B)
#define PW_TILE (64 * TSTR_B)
#define PSTAGE (2 * PA_TILE + 2 * PW_TILE)   // 53248
#define PROJ_SMEM PSTAGE
#define KSPLIT 8

__global__ void __launch_bounds__(128) proj_partial_kernel() {
    extern __shared__ char smc[];
    const uint32_t sb = smem_u32(smc);
    const int tid = threadIdx.x;
    const int lane = tid & 31;
    const int w = tid >> 5;
    const int m0w = w * 16;
    const int m0 = blockIdx.x * 64;
    const int ksplit = blockIdx.y;
    const int kbase = ksplit * (2048 / KSPLIT);

    auto load_chunk = [&](int k0) {
        for (int idx = tid; idx < 3072; idx += 128) {
            if (idx < 1024) {
                int arr = idx >> 9, r = (idx >> 3) & 63, c = idx & 7;
                const char* src = (const char*)(arr ? g_Al : g_Ah) +
                                  (long)(m0 + r) * 4096 + k0 * 2 + c * 16;
                cp16(sb + arr * PA_TILE + r * ASTR_B + c * 16, src);
            } else {
                int j = idx - 1024;
                int arr = j >> 10, r = (j >> 4) & 63, c = j & 15;
                const char* src = (const char*)(arr ? g_Wpl : g_Wph) +
                                  (long)(k0 + r) * 256 + c * 16;
                cp16(sb + 2 * PA_TILE + arr * PW_TILE + r * TSTR_B + c * 16, src);
            }
        }
    };

    const uint32_t aoffA = (uint32_t)(m0w + (lane & 15)) * ASTR_B + ((lane >> 4) << 3) * 2;
    const uint32_t voffW = (uint32_t)((lane & 8) + (lane & 7)) * TSTR_B + ((lane >> 4) << 3) * 2;

    float acc[16][4];
#pragma unroll
    for (int t = 0; t < 16; t++)
#pragma unroll
        for (int j = 0; j < 4; j++) acc[t][j] = 0.0f;

    for (int it = 0; it < 2048 / KSPLIT / 64; it++) {
        load_chunk(kbase + it * 64);
        cp_commit();
        cp_wait<0>();
        __syncthreads();

        const uint32_t AH = sb, AL = sb + PA_TILE;
        const uint32_t WH = sb + 2 * PA_TILE, WL = WH + PW_TILE;

#pragma unroll
        for (int ks = 0; ks < 4; ks++) {
            uint32_t ah[4], al[4];
            ldm_x4(ah, AH + aoffA + ks * 32);
            ldm_x4(al, AL + aoffA + ks * 32);
            uint32_t vbase = voffW + (uint32_t)(ks * 16) * TSTR_B;
#pragma unroll
            for (int nv = 0; nv < 8; nv++) {
                uint32_t bh[4], bl[4];
                ldm_x4t(bh, WH + vbase + nv * 32);
                ldm_x4t(bl, WL + vbase + nv * 32);
                mma_bf16(acc[2 * nv], ah, bh);
                mma_bf16(acc[2 * nv], ah, bl);
                mma_bf16(acc[2 * nv], al, bh);
                mma_bf16(acc[2 * nv + 1], ah, bh + 2);
                mma_bf16(acc[2 * nv + 1], ah, bl + 2);
                mma_bf16(acc[2 * nv + 1], al, bh + 2);
            }
        }
        __syncthreads();
    }

    float* P = g_Pp + (long)ksplit * (BATCH * SEQ * DIM);
    const int mr0 = m0 + m0w + (lane >> 2);
#pragma unroll
    for (int t = 0; t < 16; t++) {
        int col = t * 8 + ((lane & 3) << 1);
        *(float2*)(P + (long)mr0 * 128 + col) = make_float2(acc[t][0], acc[t][1]);
        *(float2*)(P + (long)(mr0 + 8) * 128 + col) = make_float2(acc[t][2], acc[t][3]);
    }
}

// ---------------------------------------------------------------------------
// Kernel D: reduce 8 partials -> out (fixed order, deterministic)
// ---------------------------------------------------------------------------
#define NOUT4 (BATCH * SEQ * DIM / 4)
__global__ void __launch_bounds__(256) proj_reduce_kernel(float* __restrict__ out) {
    int i = blockIdx.x * 256 + threadIdx.x;
    if (i >= NOUT4) return;
    const long stride = (long)BATCH * SEQ * DIM;
    float4 r = *(const float4*)(g_Pp + 4 * (long)i);
#pragma unroll
    for (int s = 1; s < KSPLIT; s++) {
        float4 v = *(const float4*)(g_Pp + s * stride + 4 * (long)i);
        r.x += v.x; r.y += v.y; r.z += v.z; r.w += v.w;
    }
    *(float4*)(out + 4 * (long)i) = r;
}

// ---------------------------------------------------------------------------
extern "C" void kernel_launch(void* const* d_in, const int* in_sizes, int n_in,
                              void* d_out, int out_size) {
    const float* x     = (const float*)d_in[0];
    const float* Wqkv  = (const float*)d_in[1];
    const float* Wproj = (const float*)d_in[2];
    float* out = (float*)d_out;

    prep_kernel<<<(NPX + NPQ + NPP + 255) / 256, 256>>>(x, Wqkv, Wproj);

    cudaFuncSetAttribute(qkv_kernel, cudaFuncAttributeMaxDynamicSharedMemorySize, QKV_SMEM);
    qkv_kernel<<<dim3(8192 / 64, 24), 128, QKV_SMEM>>>();

    cudaFuncSetAttribute(attn_kernel, cudaFuncAttributeMaxDynamicSharedMemorySize, ATTN_SMEM);
    attn_kernel<<<dim3(SEQ / 128, QH, BATCH), 256, ATTN_SMEM>>>();

    cudaFuncSetAttribute(proj_partial_kernel, cudaFuncAttributeMaxDynamicSharedMemorySize, PROJ_SMEM);
    proj_partial_kernel<<<dim3(8192 / 64, KSPLIT), 128, PROJ_SMEM>>>();

    proj_reduce_kernel<<<(NOUT4 + 255) / 256, 256>>>(out);
}

// round 16
// speedup vs baseline: 1.0947x; 1.0399x over previous
#include <cuda_runtime.h>
#include <cuda_bf16.h>
#include <cstdint>
#include <math.h>

#define BATCH 4
#define SEQ 2048
#define DIM 128
#define QH 16
#define KVH 4
#define WINDOW 512

// ---------------------------------------------------------------------------
// device-global scratch (allocation-free)
// ---------------------------------------------------------------------------
__device__ __nv_bfloat16 g_Xh[BATCH * SEQ * DIM];
__device__ __nv_bfloat16 g_Xl[BATCH * SEQ * DIM];
__device__ __nv_bfloat16 g_Wqh[DIM * 3072];
__device__ __nv_bfloat16 g_Wql[DIM * 3072];
__device__ __nv_bfloat16 g_Wph[2048 * DIM];
__device__ __nv_bfloat16 g_Wpl[2048 * DIM];
__device__ __nv_bfloat16 g_Qh[BATCH * QH * SEQ * DIM];
__device__ __nv_bfloat16 g_Ql[BATCH * QH * SEQ * DIM];
__device__ __nv_bfloat16 g_Kh[BATCH * KVH * SEQ * DIM];
__device__ __nv_bfloat16 g_Kl[BATCH * KVH * SEQ * DIM];
__device__ __nv_bfloat16 g_Vh[BATCH * KVH * SEQ * DIM];
__device__ __nv_bfloat16 g_Vl[BATCH * KVH * SEQ * DIM];
__device__ __nv_bfloat16 g_Ah[BATCH * SEQ * QH * DIM];
__device__ __nv_bfloat16 g_Al[BATCH * SEQ * QH * DIM];
__device__ float g_Pp[8 * BATCH * SEQ * DIM];    // proj split-K partials (32MB)

// ---------------------------------------------------------------------------
// base-ISA helpers
// ---------------------------------------------------------------------------
__device__ __forceinline__ uint32_t smem_u32(const void* p) {
    uint32_t a;
    asm("{ .reg .u64 t; cvta.to.shared.u64 t, %1; cvt.u32.u64 %0, t; }" : "=r"(a) : "l"(p));
    return a;
}
__device__ __forceinline__ void ldm_x4(uint32_t* r, uint32_t addr) {
    asm volatile("ldmatrix.sync.aligned.m8n8.x4.shared.b16 {%0,%1,%2,%3},[%4];"
        : "=r"(r[0]), "=r"(r[1]), "=r"(r[2]), "=r"(r[3]) : "r"(addr));
}
__device__ __forceinline__ void ldm_x4t(uint32_t* r, uint32_t addr) {
    asm volatile("ldmatrix.sync.aligned.m8n8.x4.trans.shared.b16 {%0,%1,%2,%3},[%4];"
        : "=r"(r[0]), "=r"(r[1]), "=r"(r[2]), "=r"(r[3]) : "r"(addr));
}
__device__ __forceinline__ void mma_bf16(float* d, const uint32_t* a, const uint32_t* b) {
    asm volatile(
        "mma.sync.aligned.m16n8k16.row.col.f32.bf16.bf16.f32 "
        "{%0,%1,%2,%3},{%4,%5,%6,%7},{%8,%9},{%0,%1,%2,%3};"
        : "+f"(d[0]), "+f"(d[1]), "+f"(d[2]), "+f"(d[3])
        : "r"(a[0]), "r"(a[1]), "r"(a[2]), "r"(a[3]), "r"(b[0]), "r"(b[1]));
}
__device__ __forceinline__ uint32_t pkbf(float lo, float hi) {
    uint32_t r; asm("cvt.rn.bf16x2.f32 %0,%1,%2;" : "=r"(r) : "f"(hi), "f"(lo)); return r;
}
__device__ __forceinline__ float btrunc(float x) {
    return __uint_as_float(__float_as_uint(x) & 0xffff0000u);
}
__device__ __forceinline__ float ex2(float x) {
    float y; asm("ex2.approx.ftz.f32 %0,%1;" : "=f"(y) : "f"(x)); return y;
}
__device__ __forceinline__ void cp16(uint32_t dst, const void* src) {
    asm volatile("cp.async.cg.shared.global [%0], [%1], 16;" :: "r"(dst), "l"(src));
}
__device__ __forceinline__ void cp_commit() { asm volatile("cp.async.commit_group;"); }
template <int N> __device__ __forceinline__ void cp_wait() {
    asm volatile("cp.async.wait_group %0;" :: "n"(N));
}
__device__ __forceinline__ void split2(float v0, float v1, uint32_t& hp, uint32_t& lp) {
    hp = pkbf(v0, v1);
    float h0 = __uint_as_float(hp << 16);
    float h1 = __uint_as_float(hp & 0xffff0000u);
    lp = pkbf(v0 - h0, v1 - h1);
}

// ---------------------------------------------------------------------------
// Kernel 0: split inputs into bf16 hi/lo
// ---------------------------------------------------------------------------
#define NPX (BATCH * SEQ * DIM / 2)
#define NPQ (DIM * 3072 / 2)
#define NPP (2048 * DIM / 2)
__global__ void __launch_bounds__(256) prep_kernel(const float* __restrict__ x,
                                                   const float* __restrict__ Wqkv,
                                                   const float* __restrict__ Wproj) {
    const float qscale = 1.4426950408889634f * 0.08838834764831845f;
    int i = blockIdx.x * 256 + threadIdx.x;
    if (i < NPX) {
        float2 v = *(const float2*)(x + 2 * i);
        uint32_t hp, lp; split2(v.x, v.y, hp, lp);
        *(uint32_t*)(g_Xh + 2 * i) = hp; *(uint32_t*)(g_Xl + 2 * i) = lp;
    } else if (i < NPX + NPQ) {
        int j = i - NPX;
        float2 v = *(const float2*)(Wqkv + 2 * j);
        int col = (2 * j) % 3072;
        if (col < QH * DIM) { v.x *= qscale; v.y *= qscale; }
        uint32_t hp, lp; split2(v.x, v.y, hp, lp);
        *(uint32_t*)(g_Wqh + 2 * j) = hp; *(uint32_t*)(g_Wql + 2 * j) = lp;
    } else if (i < NPX + NPQ + NPP) {
        int j = i - NPX - NPQ;
        float2 v = *(const float2*)(Wproj + 2 * j);
        uint32_t hp, lp; split2(v.x, v.y, hp, lp);
        *(uint32_t*)(g_Wph + 2 * j) = hp; *(uint32_t*)(g_Wpl + 2 * j) = lp;
    }
}

// ---------------------------------------------------------------------------
// Kernel A: qkv via HMMA. Block 64m x 128n (one head), 128 threads,
// single-buffered (104KB smem -> 2 CTAs/SM).
// ---------------------------------------------------------------------------
#define TSTR_B 272
#define XA_TILE (64 * TSTR_B)    // 17408
#define WB_TILE (128 * TSTR_B)   // 34816
#define QKV_SMEM (2 * XA_TILE + 2 * WB_TILE)   // 104448

__global__ void __launch_bounds__(128) qkv_kernel() {
    extern __shared__ char smc[];
    const uint32_t sb = smem_u32(smc);
    const int tid = threadIdx.x;
    const int lane = tid & 31;
    const int w = tid >> 5;
    const int m0w = w * 16;
    const int m0 = blockIdx.x * 64;
    const int head = blockIdx.y;
    const int n0 = head * 128;

    for (int idx = tid; idx < 6144; idx += 128) {
        if (idx < 2048) {
            int arr = idx >> 10, r = (idx >> 4) & 63, c = idx & 15;
            const char* src = (const char*)(arr ? g_Xl : g_Xh) + (long)(m0 + r) * 256 + c * 16;
            cp16(sb + arr * XA_TILE + r * TSTR_B + c * 16, src);
        } else {
            int j = idx - 2048;
            int arr = j >> 11, r = (j >> 4) & 127, c = j & 15;
            const char* src = (const char*)(arr ? g_Wql : g_Wqh) + ((long)r * 3072 + n0) * 2 + c * 16;
            cp16(sb + 2 * XA_TILE + arr * WB_TILE + r * TSTR_B + c * 16, src);
        }
    }
    cp_commit();
    cp_wait<0>();
    __syncthreads();

    const uint32_t XH = sb, XL = sb + XA_TILE;
    const uint32_t WH = sb + 2 * XA_TILE, WL = WH + WB_TILE;
    const uint32_t aoff = (uint32_t)(m0w + (lane & 15)) * TSTR_B + ((lane >> 4) << 3) * 2;
    const uint32_t voff = (uint32_t)((lane & 8) + (lane & 7)) * TSTR_B + ((lane >> 4) << 3) * 2;

    float acc[16][4];
#pragma unroll
    for (int t = 0; t < 16; t++)
#pragma unroll
        for (int j = 0; j < 4; j++) acc[t][j] = 0.0f;

#pragma unroll
    for (int ks = 0; ks < 8; ks++) {
        uint32_t ah[4], al[4];
        ldm_x4(ah, XH + aoff + ks * 32);
        ldm_x4(al, XL + aoff + ks * 32);
        uint32_t vbase = voff + (uint32_t)(ks * 16) * TSTR_B;
#pragma unroll
        for (int nv = 0; nv < 8; nv++) {
            uint32_t bh[4], bl[4];
            ldm_x4t(bh, WH + vbase + nv * 32);
            ldm_x4t(bl, WL + vbase + nv * 32);
            mma_bf16(acc[2 * nv], ah, bh);
            mma_bf16(acc[2 * nv], ah, bl);
            mma_bf16(acc[2 * nv], al, bh);
            mma_bf16(acc[2 * nv + 1], ah, bh + 2);
            mma_bf16(acc[2 * nv + 1], ah, bl + 2);
            mma_bf16(acc[2 * nv + 1], al, bh + 2);
        }
    }

    __nv_bfloat16 *dh, *dl;
    int hh, nheads;
    if (head < QH)            { dh = g_Qh; dl = g_Ql; hh = head;            nheads = QH; }
    else if (head < QH + KVH) { dh = g_Kh; dl = g_Kl; hh = head - QH;       nheads = KVH; }
    else                      { dh = g_Vh; dl = g_Vl; hh = head - QH - KVH; nheads = KVH; }

    const int mr0 = m0 + m0w + (lane >> 2);
#pragma unroll
    for (int half = 0; half < 2; half++) {
        int m = mr0 + half * 8;
        int b = m >> 11, s = m & 2047;
        long rowo = ((long)(b * nheads + hh) * SEQ + s) * DIM + ((lane & 3) << 1);
#pragma unroll
        for (int t = 0; t < 16; t++) {
            uint32_t hp, lp;
            split2(acc[t][2 * half], acc[t][2 * half + 1], hp, lp);
            *(uint32_t*)(dh + rowo + t * 8) = hp;
            *(uint32_t*)(dl + rowo + t * 8) = lp;
        }
    }
}

// ---------------------------------------------------------------------------
// Kernel B: flash attention, 64-row q-blocks, 128 threads, single-buffered KV
// (104KB smem -> 2 CTAs/SM; cross-CTA overlap replaces intra-CTA prefetch).
// ---------------------------------------------------------------------------
#define AQ_BYTES (64 * TSTR_B)          // 17408 per Q array
#define KV_TILE_B (64 * TSTR_B)
#define AST_OFF (2 * AQ_BYTES)          // 34816
#define ATTN_SMEM (AST_OFF + 4 * KV_TILE_B)   // 104448

__global__ void __launch_bounds__(128) attn_kernel() {
    extern __shared__ char smc[];
    const uint32_t sb = smem_u32(smc);
    const int tid = threadIdx.x;
    const int lane = tid & 31;
    const int w = tid >> 5;
    const int m0w = w * 16;

    const int qt = (SEQ / 64 - 1) - blockIdx.x;   // big blocks first
    const int h  = blockIdx.y;
    const int b  = blockIdx.z;
    const int g  = h >> 2;
    const int q0 = qt * 64;
    const float slope2 = exp2f(-(float)(h + 1) * 0.5f) * 1.4426950408889634f;

    const __nv_bfloat16* Qhg = g_Qh + ((long)(b * QH + h) * SEQ + q0) * DIM;
    const __nv_bfloat16* Qlg = g_Ql + ((long)(b * QH + h) * SEQ + q0) * DIM;
    const __nv_bfloat16* Khg = g_Kh + (long)(b * KVH + g) * SEQ * DIM;
    const __nv_bfloat16* Klg = g_Kl + (long)(b * KVH + g) * SEQ * DIM;
    const __nv_bfloat16* Vhg = g_Vh + (long)(b * KVH + g) * SEQ * DIM;
    const __nv_bfloat16* Vlg = g_Vl + (long)(b * KVH + g) * SEQ * DIM;

    const int ktlo = (q0 >= WINDOW) ? (q0 - WINDOW) : 0;
    const int nt = (q0 + 64 - ktlo) >> 6;

    // prologue: Q (2 arrays x 64 rows) + KV tile 0, one group
    for (int idx = tid; idx < 2048; idx += 128) {
        int arr = idx >> 10, r = (idx >> 4) & 63, c = idx & 15;
        const char* src = (const char*)(arr ? Qlg : Qhg) + r * 256 + c * 16;
        cp16(sb + arr * AQ_BYTES + r * TSTR_B + c * 16, src);
    }
    {
        const __nv_bfloat16* srcs[4] = { Khg, Klg, Vhg, Vlg };
        for (int idx = tid; idx < 4096; idx += 128) {
            int arr = idx >> 10, r = (idx >> 4) & 63, c = idx & 15;
            cp16(sb + AST_OFF + arr * KV_TILE_B + r * TSTR_B + c * 16,
                 (const char*)srcs[arr] + (long)(ktlo + r) * 256 + c * 16);
        }
    }
    cp_commit();
    cp_wait<0>();
    __syncthreads();

    float m0r = -1e30f, m1r = -1e30f, l0 = 0.0f, l1 = 0.0f;
    float oacc[16][4];
#pragma unroll
    for (int t = 0; t < 16; t++)
#pragma unroll
        for (int j = 0; j < 4; j++) oacc[t][j] = 0.0f;

    const int qr0 = q0 + m0w + (lane >> 2);
    const int qr1 = qr0 + 8;
    const int wq_lo = q0 + m0w;
    const int wq_hi = q0 + m0w + 15;

    const uint32_t aoff = (uint32_t)(m0w + (lane & 15)) * TSTR_B + ((lane >> 4) << 3) * 2;
    const uint32_t boff_n = (uint32_t)(((lane >> 4) << 3) + (lane & 7)) * TSTR_B + (lane & 8) * 2;
    const uint32_t voff_r = (uint32_t)((lane & 8) + (lane & 7)) * TSTR_B + ((lane >> 4) << 3) * 2;

    const uint32_t KHO = sb + AST_OFF, KLO = KHO + KV_TILE_B;
    const uint32_t VHO = KHO + 2 * KV_TILE_B, VLO = KHO + 3 * KV_TILE_B;

    for (int it = 0; it < nt; it++) {
        const int kt = ktlo + it * 64;

        // warp-level dead-tile skip (exact: all P == 0 for this warp)
        const bool act = (kt <= wq_hi) && (kt + 63 >= wq_lo - WINDOW);
        if (act) {
            float sacc[8][4];
#pragma unroll
            for (int t = 0; t < 8; t++)
#pragma unroll
                for (int j = 0; j < 4; j++) sacc[t][j] = 0.0f;

#pragma unroll
            for (int ks = 0; ks < 8; ks++) {
                uint32_t ah[4], al[4];
                ldm_x4(ah, sb + aoff + ks * 32);
                ldm_x4(al, sb + AQ_BYTES + aoff + ks * 32);
#pragma unroll
                for (int ntl = 0; ntl < 4; ntl++) {
                    uint32_t bh[4], bl[4];
                    uint32_t bo = boff_n + (uint32_t)(ntl * 16) * TSTR_B + ks * 32;
                    ldm_x4(bh, KHO + bo);
                    ldm_x4(bl, KLO + bo);
                    mma_bf16(sacc[2 * ntl], ah, bh);
                    mma_bf16(sacc[2 * ntl], ah, bl);
                    mma_bf16(sacc[2 * ntl], al, bh);
                    mma_bf16(sacc[2 * ntl + 1], ah, bh + 2);
                    mma_bf16(sacc[2 * ntl + 1], ah, bl + 2);
                    mma_bf16(sacc[2 * ntl + 1], al, bh + 2);
                }
            }

            // ---- ALiBi + mask (fast path for fully-valid tiles) ----
            const bool allvalid = (kt + 63 <= wq_lo) && (kt >= wq_hi - WINDOW);
            if (allvalid) {
                const float f0 = slope2 * (float)(qr0 - kt - ((lane & 3) << 1));
                const float f1 = f0 - slope2;
                const float f2 = f0 + 8.0f * slope2;
                const float f3 = f2 - slope2;
#pragma unroll
                for (int t = 0; t < 8; t++) {
                    const float dt = (float)(8 * t) * slope2;
                    sacc[t][0] += f0 - dt;
                    sacc[t][1] += f1 - dt;
                    sacc[t][2] += f2 - dt;
                    sacc[t][3] += f3 - dt;
                }
            } else {
#pragma unroll
                for (int t = 0; t < 8; t++) {
                    int c0 = kt + t * 8 + ((lane & 3) << 1);
                    int c1 = c0 + 1;
                    int d00 = qr0 - c0, d01 = qr0 - c1, d10 = qr1 - c0, d11 = qr1 - c1;
                    sacc[t][0] = (d00 >= 0 && d00 <= WINDOW) ? sacc[t][0] + slope2 * (float)d00 : -1e32f;
                    sacc[t][1] = (d01 >= 0 && d01 <= WINDOW) ? sacc[t][1] + slope2 * (float)d01 : -1e32f;
                    sacc[t][2] = (d10 >= 0 && d10 <= WINDOW) ? sacc[t][2] + slope2 * (float)d10 : -1e32f;
                    sacc[t][3] = (d11 >= 0 && d11 <= WINDOW) ? sacc[t][3] + slope2 * (float)d11 : -1e32f;
                }
            }

            float mx0 = -1e32f, mx1 = -1e32f;
#pragma unroll
            for (int t = 0; t < 8; t++) {
                mx0 = fmaxf(mx0, fmaxf(sacc[t][0], sacc[t][1]));
                mx1 = fmaxf(mx1, fmaxf(sacc[t][2], sacc[t][3]));
            }
            mx0 = fmaxf(mx0, __shfl_xor_sync(0xffffffffu, mx0, 1));
            mx0 = fmaxf(mx0, __shfl_xor_sync(0xffffffffu, mx0, 2));
            mx1 = fmaxf(mx1, __shfl_xor_sync(0xffffffffu, mx1, 1));
            mx1 = fmaxf(mx1, __shfl_xor_sync(0xffffffffu, mx1, 2));
            float mn0 = fmaxf(m0r, mx0), mn1 = fmaxf(m1r, mx1);
            float a0 = ex2(m0r - mn0), a1 = ex2(m1r - mn1);
            m0r = mn0; m1r = mn1;

            float ps0 = 0.0f, ps1 = 0.0f;
#pragma unroll
            for (int t = 0; t < 8; t++) {
                sacc[t][0] = ex2(sacc[t][0] - mn0);
                sacc[t][1] = ex2(sacc[t][1] - mn0);
                sacc[t][2] = ex2(sacc[t][2] - mn1);
                sacc[t][3] = ex2(sacc[t][3] - mn1);
                ps0 += sacc[t][0] + sacc[t][1];
                ps1 += sacc[t][2] + sacc[t][3];
            }
            l0 = l0 * a0 + ps0;
            l1 = l1 * a1 + ps1;
#pragma unroll
            for (int t = 0; t < 16; t++) {
                oacc[t][0] *= a0; oacc[t][1] *= a0;
                oacc[t][2] *= a1; oacc[t][3] *= a1;
            }

            // ---- O += P V (no per-kp control flow) ----
#pragma unroll
            for (int kp = 0; kp < 4; kp++) {
                const float* s0 = sacc[2 * kp];
                const float* s1 = sacc[2 * kp + 1];
                uint32_t aPh[4], aPl[4];
                aPh[0] = __byte_perm(__float_as_uint(s0[0]), __float_as_uint(s0[1]), 0x7632);
                aPh[1] = __byte_perm(__float_as_uint(s0[2]), __float_as_uint(s0[3]), 0x7632);
                aPh[2] = __byte_perm(__float_as_uint(s1[0]), __float_as_uint(s1[1]), 0x7632);
                aPh[3] = __byte_perm(__float_as_uint(s1[2]), __float_as_uint(s1[3]), 0x7632);
                aPl[0] = pkbf(s0[0] - btrunc(s0[0]), s0[1] - btrunc(s0[1]));
                aPl[1] = pkbf(s0[2] - btrunc(s0[2]), s0[3] - btrunc(s0[3]));
                aPl[2] = pkbf(s1[0] - btrunc(s1[0]), s1[1] - btrunc(s1[1]));
                aPl[3] = pkbf(s1[2] - btrunc(s1[2]), s1[3] - btrunc(s1[3]));

                uint32_t vbase = voff_r + (uint32_t)(kp * 16) * TSTR_B;
#pragma unroll
                for (int nv = 0; nv < 8; nv++) {
                    uint32_t bvh[4], bvl[4];
                    uint32_t vo = vbase + nv * 32;
                    ldm_x4t(bvh, VHO + vo);
                    ldm_x4t(bvl, VLO + vo);
                    mma_bf16(oacc[2 * nv], aPh, bvh);
                    mma_bf16(oacc[2 * nv], aPh, bvl);
                    mma_bf16(oacc[2 * nv], aPl, bvh);
                    mma_bf16(oacc[2 * nv + 1], aPh, bvh + 2);
                    mma_bf16(oacc[2 * nv + 1], aPh, bvl + 2);
                    mma_bf16(oacc[2 * nv + 1], aPl, bvh + 2);
                }
            }
        }

        // reload the single KV buffer for the next tile
        if (it + 1 < nt) {
            const int ktn = kt + 64;
            __syncthreads();   // all warps done reading current KV
            const __nv_bfloat16* srcs[4] = { Khg, Klg, Vhg, Vlg };
            for (int idx = tid; idx < 4096; idx += 128) {
                int arr = idx >> 10, r = (idx >> 4) & 63, c = idx & 15;
                cp16(sb + AST_OFF + arr * KV_TILE_B + r * TSTR_B + c * 16,
                     (const char*)srcs[arr] + (long)(ktn + r) * 256 + c * 16);
            }
            cp_commit();
            cp_wait<0>();
            __syncthreads();
        }
    }

    l0 += __shfl_xor_sync(0xffffffffu, l0, 1);
    l0 += __shfl_xor_sync(0xffffffffu, l0, 2);
    l1 += __shfl_xor_sync(0xffffffffu, l1, 1);
    l1 += __shfl_xor_sync(0xffffffffu, l1, 2);
    const float i0 = 1.0f / l0, i1 = 1.0f / l1;

    long r0 = ((long)b * SEQ + qr0) * (QH * DIM) + h * DIM + ((lane & 3) << 1);
    long r1 = ((long)b * SEQ + qr1) * (QH * DIM) + h * DIM + ((lane & 3) << 1);
#pragma unroll
    for (int t = 0; t < 16; t++) {
        uint32_t hp, lp;
        split2(oacc[t][0] * i0, oacc[t][1] * i0, hp, lp);
        *(uint32_t*)(g_Ah + r0 + t * 8) = hp;
        *(uint32_t*)(g_Al + r0 + t * 8) = lp;
        split2(oacc[t][2] * i1, oacc[t][3] * i1, hp, lp);
        *(uint32_t*)(g_Ah + r1 + t * 8) = hp;
        *(uint32_t*)(g_Al + r1 + t * 8) = lp;
    }
}

// ---------------------------------------------------------------------------
// Kernel C: proj split-K=8 partials. Single-buffered, 4 CTAs/SM.
// ---------------------------------------------------------------------------
#define ASTR_B 144
#define PA_TILE (64 * ASTR_B)
#define PW_TILE (64 * TSTR_B)
#define PSTAGE (2 * PA_TILE + 2 * PW_TILE)   // 53248
#define PROJ_SMEM PSTAGE
#define KSPLIT 8

__global__ void __launch_bounds__(128) proj_partial_kernel() {
    extern __shared__ char smc[];
    const uint32_t sb = smem_u32(smc);
    const int tid = threadIdx.x;
    const int lane = tid & 31;
    const int w = tid >> 5;
    const int m0w = w * 16;
    const int m0 = blockIdx.x * 64;
    const int ksplit = blockIdx.y;
    const int kbase = ksplit * (2048 / KSPLIT);

    auto load_chunk = [&](int k0) {
        for (int idx = tid; idx < 3072; idx += 128) {
            if (idx < 1024) {
                int arr = idx >> 9, r = (idx >> 3) & 63, c = idx & 7;
                const char* src = (const char*)(arr ? g_Al : g_Ah) +
                                  (long)(m0 + r) * 4096 + k0 * 2 + c * 16;
                cp16(sb + arr * PA_TILE + r * ASTR_B + c * 16, src);
            } else {
                int j = idx - 1024;
                int arr = j >> 10, r = (j >> 4) & 63, c = j & 15;
                const char* src = (const char*)(arr ? g_Wpl : g_Wph) +
                                  (long)(k0 + r) * 256 + c * 16;
                cp16(sb + 2 * PA_TILE + arr * PW_TILE + r * TSTR_B + c * 16, src);
            }
        }
    };

    const uint32_t aoffA = (uint32_t)(m0w + (lane & 15)) * ASTR_B + ((lane >> 4) << 3) * 2;
    const uint32_t voffW = (uint32_t)((lane & 8) + (lane & 7)) * TSTR_B + ((lane >> 4) << 3) * 2;

    float acc[16][4];
#pragma unroll
    for (int t = 0; t < 16; t++)
#pragma unroll
        for (int j = 0; j < 4; j++) acc[t][j] = 0.0f;

    for (int it = 0; it < 2048 / KSPLIT / 64; it++) {
        load_chunk(kbase + it * 64);
        cp_commit();
        cp_wait<0>();
        __syncthreads();

        const uint32_t AH = sb, AL = sb + PA_TILE;
        const uint32_t WH = sb + 2 * PA_TILE, WL = WH + PW_TILE;

#pragma unroll
        for (int ks = 0; ks < 4; ks++) {
            uint32_t ah[4], al[4];
            ldm_x4(ah, AH + aoffA + ks * 32);
            ldm_x4(al, AL + aoffA + ks * 32);
            uint32_t vbase = voffW + (uint32_t)(ks * 16) * TSTR_B;
#pragma unroll
            for (int nv = 0; nv < 8; nv++) {
                uint32_t bh[4], bl[4];
                ldm_x4t(bh, WH + vbase + nv * 32);
                ldm_x4t(bl, WL + vbase + nv * 32);
                mma_bf16(acc[2 * nv], ah, bh);
                mma_bf16(acc[2 * nv], ah, bl);
                mma_bf16(acc[2 * nv], al, bh);
                mma_bf16(acc[2 * nv + 1], ah, bh + 2);
                mma_bf16(acc[2 * nv + 1], ah, bl + 2);
                mma_bf16(acc[2 * nv + 1], al, bh + 2);
            }
        }
        __syncthreads();
    }

    float* P = g_Pp + (long)ksplit * (BATCH * SEQ * DIM);
    const int mr0 = m0 + m0w + (lane >> 2);
#pragma unroll
    for (int t = 0; t < 16; t++) {
        int col = t * 8 + ((lane & 3) << 1);
        *(float2*)(P + (long)mr0 * 128 + col) = make_float2(acc[t][0], acc[t][1]);
        *(float2*)(P + (long)(mr0 + 8) * 128 + col) = make_float2(acc[t][2], acc[t][3]);
    }
}

// ---------------------------------------------------------------------------
// Kernel D: reduce 8 partials -> out (fixed order, deterministic)
// ---------------------------------------------------------------------------
#define NOUT4 (BATCH * SEQ * DIM / 4)
__global__ void __launch_bounds__(256) proj_reduce_kernel(float* __restrict__ out) {
    int i = blockIdx.x * 256 + threadIdx.x;
    if (i >= NOUT4) return;
    const long stride = (long)BATCH * SEQ * DIM;
    float4 r = *(const float4*)(g_Pp + 4 * (long)i);
#pragma unroll
    for (int s = 1; s < KSPLIT; s++) {
        float4 v = *(const float4*)(g_Pp + s * stride + 4 * (long)i);
        r.x += v.x; r.y += v.y; r.z += v.z; r.w += v.w;
    }
    *(float4*)(out + 4 * (long)i) = r;
}

// ---------------------------------------------------------------------------
extern "C" void kernel_launch(void* const* d_in, const int* in_sizes, int n_in,
                              void* d_out, int out_size) {
    const float* x     = (const float*)d_in[0];
    const float* Wqkv  = (const float*)d_in[1];
    const float* Wproj = (const float*)d_in[2];
    float* out = (float*)d_out;

    prep_kernel<<<(NPX + NPQ + NPP + 255) / 256, 256>>>(x, Wqkv, Wproj);

    cudaFuncSetAttribute(qkv_kernel, cudaFuncAttributeMaxDynamicSharedMemorySize, QKV_SMEM);
    qkv_kernel<<<dim3(8192 / 64, 24), 128, QKV_SMEM>>>();

    cudaFuncSetAttribute(attn_kernel, cudaFuncAttributeMaxDynamicSharedMemorySize, ATTN_SMEM);
    attn_kernel<<<dim3(SEQ / 64, QH, BATCH), 128, ATTN_SMEM>>>();

    cudaFuncSetAttribute(proj_partial_kernel, cudaFuncAttributeMaxDynamicSharedMemorySize, PROJ_SMEM);
    proj_partial_kernel<<<dim3(8192 / 64, KSPLIT), 128, PROJ_SMEM>>>();

    proj_reduce_kernel<<<(NOUT4 + 255) / 256, 256>>>(out);
}

// round 17
// speedup vs baseline: 1.1165x; 1.0199x over previous
#include <cuda_runtime.h>
#include <cuda_bf16.h>
#include <cstdint>
#include <math.h>

#define BATCH 4
#define SEQ 2048
#define DIM 128
#define QH 16
#define KVH 4
#define WINDOW 512

// ---------------------------------------------------------------------------
// device-global scratch (allocation-free)
// ---------------------------------------------------------------------------
__device__ __nv_bfloat16 g_Xh[BATCH * SEQ * DIM];
__device__ __nv_bfloat16 g_Xl[BATCH * SEQ * DIM];
__device__ __nv_bfloat16 g_Wqh[DIM * 3072];
__device__ __nv_bfloat16 g_Wql[DIM * 3072];
__device__ __nv_bfloat16 g_Wph[2048 * DIM];
__device__ __nv_bfloat16 g_Wpl[2048 * DIM];
__device__ __nv_bfloat16 g_Qh[BATCH * QH * SEQ * DIM];
__device__ __nv_bfloat16 g_Ql[BATCH * QH * SEQ * DIM];
__device__ __nv_bfloat16 g_Kh[BATCH * KVH * SEQ * DIM];
__device__ __nv_bfloat16 g_Kl[BATCH * KVH * SEQ * DIM];
__device__ __nv_bfloat16 g_Vh[BATCH * KVH * SEQ * DIM];
__device__ __nv_bfloat16 g_Vl[BATCH * KVH * SEQ * DIM];
__device__ __nv_bfloat16 g_Ah[BATCH * SEQ * QH * DIM];
__device__ __nv_bfloat16 g_Al[BATCH * SEQ * QH * DIM];
__device__ float g_Pp[8 * BATCH * SEQ * DIM];    // proj split-K partials (32MB)

// ---------------------------------------------------------------------------
// base-ISA helpers
// ---------------------------------------------------------------------------
__device__ __forceinline__ uint32_t smem_u32(const void* p) {
    uint32_t a;
    asm("{ .reg .u64 t; cvta.to.shared.u64 t, %1; cvt.u32.u64 %0, t; }" : "=r"(a) : "l"(p));
    return a;
}
__device__ __forceinline__ void ldm_x4(uint32_t* r, uint32_t addr) {
    asm volatile("ldmatrix.sync.aligned.m8n8.x4.shared.b16 {%0,%1,%2,%3},[%4];"
        : "=r"(r[0]), "=r"(r[1]), "=r"(r[2]), "=r"(r[3]) : "r"(addr));
}
__device__ __forceinline__ void ldm_x4t(uint32_t* r, uint32_t addr) {
    asm volatile("ldmatrix.sync.aligned.m8n8.x4.trans.shared.b16 {%0,%1,%2,%3},[%4];"
        : "=r"(r[0]), "=r"(r[1]), "=r"(r[2]), "=r"(r[3]) : "r"(addr));
}
__device__ __forceinline__ void mma_bf16(float* d, const uint32_t* a, const uint32_t* b) {
    asm volatile(
        "mma.sync.aligned.m16n8k16.row.col.f32.bf16.bf16.f32 "
        "{%0,%1,%2,%3},{%4,%5,%6,%7},{%8,%9},{%0,%1,%2,%3};"
        : "+f"(d[0]), "+f"(d[1]), "+f"(d[2]), "+f"(d[3])
        : "r"(a[0]), "r"(a[1]), "r"(a[2]), "r"(a[3]), "r"(b[0]), "r"(b[1]));
}
__device__ __forceinline__ uint32_t pkbf(float lo, float hi) {
    uint32_t r; asm("cvt.rn.bf16x2.f32 %0,%1,%2;" : "=r"(r) : "f"(hi), "f"(lo)); return r;
}
__device__ __forceinline__ float btrunc(float x) {
    return __uint_as_float(__float_as_uint(x) & 0xffff0000u);
}
__device__ __forceinline__ float ex2(float x) {
    float y; asm("ex2.approx.ftz.f32 %0,%1;" : "=f"(y) : "f"(x)); return y;
}
__device__ __forceinline__ void cp16(uint32_t dst, const void* src) {
    asm volatile("cp.async.cg.shared.global [%0], [%1], 16;" :: "r"(dst), "l"(src));
}
__device__ __forceinline__ void cp_commit() { asm volatile("cp.async.commit_group;"); }
template <int N> __device__ __forceinline__ void cp_wait() {
    asm volatile("cp.async.wait_group %0;" :: "n"(N));
}
__device__ __forceinline__ void split2(float v0, float v1, uint32_t& hp, uint32_t& lp) {
    hp = pkbf(v0, v1);
    float h0 = __uint_as_float(hp << 16);
    float h1 = __uint_as_float(hp & 0xffff0000u);
    lp = pkbf(v0 - h0, v1 - h1);
}

// ---------------------------------------------------------------------------
// Kernel 0: split inputs into bf16 hi/lo
// ---------------------------------------------------------------------------
#define NPX (BATCH * SEQ * DIM / 2)
#define NPQ (DIM * 3072 / 2)
#define NPP (2048 * DIM / 2)
__global__ void __launch_bounds__(256) prep_kernel(const float* __restrict__ x,
                                                   const float* __restrict__ Wqkv,
                                                   const float* __restrict__ Wproj) {
    const float qscale = 1.4426950408889634f * 0.08838834764831845f;
    int i = blockIdx.x * 256 + threadIdx.x;
    if (i < NPX) {
        float2 v = *(const float2*)(x + 2 * i);
        uint32_t hp, lp; split2(v.x, v.y, hp, lp);
        *(uint32_t*)(g_Xh + 2 * i) = hp; *(uint32_t*)(g_Xl + 2 * i) = lp;
    } else if (i < NPX + NPQ) {
        int j = i - NPX;
        float2 v = *(const float2*)(Wqkv + 2 * j);
        int col = (2 * j) % 3072;
        if (col < QH * DIM) { v.x *= qscale; v.y *= qscale; }
        uint32_t hp, lp; split2(v.x, v.y, hp, lp);
        *(uint32_t*)(g_Wqh + 2 * j) = hp; *(uint32_t*)(g_Wql + 2 * j) = lp;
    } else if (i < NPX + NPQ + NPP) {
        int j = i - NPX - NPQ;
        float2 v = *(const float2*)(Wproj + 2 * j);
        uint32_t hp, lp; split2(v.x, v.y, hp, lp);
        *(uint32_t*)(g_Wph + 2 * j) = hp; *(uint32_t*)(g_Wpl + 2 * j) = lp;
    }
}

// ---------------------------------------------------------------------------
// Kernel A: qkv via HMMA. Block 64m x 128n (one head), 128 threads.
// W loaded in two 64-k-row phases reusing one buffer:
// smem 69632 -> 3 CTAs/SM.
// ---------------------------------------------------------------------------
#define TSTR_B 272
#define XA_TILE (64 * TSTR_B)    // 17408
#define WH_TILE (64 * TSTR_B)    // 17408 (half of W k-rows)
#define QKV_SMEM (2 * XA_TILE + 2 * WH_TILE)   // 69632

__global__ void __launch_bounds__(128) qkv_kernel() {
    extern __shared__ char smc[];
    const uint32_t sb = smem_u32(smc);
    const int tid = threadIdx.x;
    const int lane = tid & 31;
    const int w = tid >> 5;
    const int m0w = w * 16;
    const int m0 = blockIdx.x * 64;
    const int head = blockIdx.y;
    const int n0 = head * 128;

    // prologue: X (2 arrays x 64 rows) + W k-rows 0..63
    for (int idx = tid; idx < 4096; idx += 128) {
        if (idx < 2048) {
            int arr = idx >> 10, r = (idx >> 4) & 63, c = idx & 15;
            const char* src = (const char*)(arr ? g_Xl : g_Xh) + (long)(m0 + r) * 256 + c * 16;
            cp16(sb + arr * XA_TILE + r * TSTR_B + c * 16, src);
        } else {
            int j = idx - 2048;
            int arr = j >> 10, r = (j >> 4) & 63, c = j & 15;
            const char* src = (const char*)(arr ? g_Wql : g_Wqh) + ((long)r * 3072 + n0) * 2 + c * 16;
            cp16(sb + 2 * XA_TILE + arr * WH_TILE + r * TSTR_B + c * 16, src);
        }
    }
    cp_commit();
    cp_wait<0>();
    __syncthreads();

    const uint32_t XH = sb, XL = sb + XA_TILE;
    const uint32_t WH = sb + 2 * XA_TILE, WL = WH + WH_TILE;
    const uint32_t aoff = (uint32_t)(m0w + (lane & 15)) * TSTR_B + ((lane >> 4) << 3) * 2;
    const uint32_t voff = (uint32_t)((lane & 8) + (lane & 7)) * TSTR_B + ((lane >> 4) << 3) * 2;

    float acc[16][4];
#pragma unroll
    for (int t = 0; t < 16; t++)
#pragma unroll
        for (int j = 0; j < 4; j++) acc[t][j] = 0.0f;

#pragma unroll
    for (int ph = 0; ph < 2; ph++) {
#pragma unroll
        for (int ks2 = 0; ks2 < 4; ks2++) {
            int ks = ph * 4 + ks2;               // global k-step (A operand)
            uint32_t ah[4], al[4];
            ldm_x4(ah, XH + aoff + ks * 32);
            ldm_x4(al, XL + aoff + ks * 32);
            uint32_t vbase = voff + (uint32_t)(ks2 * 16) * TSTR_B;  // local W row
#pragma unroll
            for (int nv = 0; nv < 8; nv++) {
                uint32_t bh[4], bl[4];
                ldm_x4t(bh, WH + vbase + nv * 32);
                ldm_x4t(bl, WL + vbase + nv * 32);
                mma_bf16(acc[2 * nv], ah, bh);
                mma_bf16(acc[2 * nv], ah, bl);
                mma_bf16(acc[2 * nv], al, bh);
                mma_bf16(acc[2 * nv + 1], ah, bh + 2);
                mma_bf16(acc[2 * nv + 1], ah, bl + 2);
                mma_bf16(acc[2 * nv + 1], al, bh + 2);
            }
        }
        if (ph == 0) {
            // reload W buffer with k-rows 64..127
            __syncthreads();
            for (int idx = tid; idx < 2048; idx += 128) {
                int arr = idx >> 10, r = (idx >> 4) & 63, c = idx & 15;
                const char* src = (const char*)(arr ? g_Wql : g_Wqh) +
                                  ((long)(r + 64) * 3072 + n0) * 2 + c * 16;
                cp16(sb + 2 * XA_TILE + arr * WH_TILE + r * TSTR_B + c * 16, src);
            }
            cp_commit();
            cp_wait<0>();
            __syncthreads();
        }
    }

    __nv_bfloat16 *dh, *dl;
    int hh, nheads;
    if (head < QH)            { dh = g_Qh; dl = g_Ql; hh = head;            nheads = QH; }
    else if (head < QH + KVH) { dh = g_Kh; dl = g_Kl; hh = head - QH;       nheads = KVH; }
    else                      { dh = g_Vh; dl = g_Vl; hh = head - QH - KVH; nheads = KVH; }

    const int mr0 = m0 + m0w + (lane >> 2);
#pragma unroll
    for (int half = 0; half < 2; half++) {
        int m = mr0 + half * 8;
        int b = m >> 11, s = m & 2047;
        long rowo = ((long)(b * nheads + hh) * SEQ + s) * DIM + ((lane & 3) << 1);
#pragma unroll
        for (int t = 0; t < 16; t++) {
            uint32_t hp, lp;
            split2(acc[t][2 * half], acc[t][2 * half + 1], hp, lp);
            *(uint32_t*)(dh + rowo + t * 8) = hp;
            *(uint32_t*)(dl + rowo + t * 8) = lp;
        }
    }
}

// ---------------------------------------------------------------------------
// Kernel B: flash attention, 64-row q-blocks, 128 threads, single-buffered KV
// (2 CTAs/SM) + warp-vote exact rescale skip.
// ---------------------------------------------------------------------------
#define AQ_BYTES (64 * TSTR_B)
#define KV_TILE_B (64 * TSTR_B)
#define AST_OFF (2 * AQ_BYTES)
#define ATTN_SMEM (AST_OFF + 4 * KV_TILE_B)   // 104448

__global__ void __launch_bounds__(128) attn_kernel() {
    extern __shared__ char smc[];
    const uint32_t sb = smem_u32(smc);
    const int tid = threadIdx.x;
    const int lane = tid & 31;
    const int w = tid >> 5;
    const int m0w = w * 16;

    const int qt = (SEQ / 64 - 1) - blockIdx.x;   // big blocks first
    const int h  = blockIdx.y;
    const int b  = blockIdx.z;
    const int g  = h >> 2;
    const int q0 = qt * 64;
    const float slope2 = exp2f(-(float)(h + 1) * 0.5f) * 1.4426950408889634f;

    const __nv_bfloat16* Qhg = g_Qh + ((long)(b * QH + h) * SEQ + q0) * DIM;
    const __nv_bfloat16* Qlg = g_Ql + ((long)(b * QH + h) * SEQ + q0) * DIM;
    const __nv_bfloat16* Khg = g_Kh + (long)(b * KVH + g) * SEQ * DIM;
    const __nv_bfloat16* Klg = g_Kl + (long)(b * KVH + g) * SEQ * DIM;
    const __nv_bfloat16* Vhg = g_Vh + (long)(b * KVH + g) * SEQ * DIM;
    const __nv_bfloat16* Vlg = g_Vl + (long)(b * KVH + g) * SEQ * DIM;

    const int ktlo = (q0 >= WINDOW) ? (q0 - WINDOW) : 0;
    const int nt = (q0 + 64 - ktlo) >> 6;

    for (int idx = tid; idx < 2048; idx += 128) {
        int arr = idx >> 10, r = (idx >> 4) & 63, c = idx & 15;
        const char* src = (const char*)(arr ? Qlg : Qhg) + r * 256 + c * 16;
        cp16(sb + arr * AQ_BYTES + r * TSTR_B + c * 16, src);
    }
    {
        const __nv_bfloat16* srcs[4] = { Khg, Klg, Vhg, Vlg };
        for (int idx = tid; idx < 4096; idx += 128) {
            int arr = idx >> 10, r = (idx >> 4) & 63, c = idx & 15;
            cp16(sb + AST_OFF + arr * KV_TILE_B + r * TSTR_B + c * 16,
                 (const char*)srcs[arr] + (long)(ktlo + r) * 256 + c * 16);
        }
    }
    cp_commit();
    cp_wait<0>();
    __syncthreads();

    float m0r = -1e30f, m1r = -1e30f, l0 = 0.0f, l1 = 0.0f;
    float oacc[16][4];
#pragma unroll
    for (int t = 0; t < 16; t++)
#pragma unroll
        for (int j = 0; j < 4; j++) oacc[t][j] = 0.0f;

    const int qr0 = q0 + m0w + (lane >> 2);
    const int qr1 = qr0 + 8;
    const int wq_lo = q0 + m0w;
    const int wq_hi = q0 + m0w + 15;

    const uint32_t aoff = (uint32_t)(m0w + (lane & 15)) * TSTR_B + ((lane >> 4) << 3) * 2;
    const uint32_t boff_n = (uint32_t)(((lane >> 4) << 3) + (lane & 7)) * TSTR_B + (lane & 8) * 2;
    const uint32_t voff_r = (uint32_t)((lane & 8) + (lane & 7)) * TSTR_B + ((lane >> 4) << 3) * 2;

    const uint32_t KHO = sb + AST_OFF, KLO = KHO + KV_TILE_B;
    const uint32_t VHO = KHO + 2 * KV_TILE_B, VLO = KHO + 3 * KV_TILE_B;

    for (int it = 0; it < nt; it++) {
        const int kt = ktlo + it * 64;

        const bool act = (kt <= wq_hi) && (kt + 63 >= wq_lo - WINDOW);
        if (act) {
            float sacc[8][4];
#pragma unroll
            for (int t = 0; t < 8; t++)
#pragma unroll
                for (int j = 0; j < 4; j++) sacc[t][j] = 0.0f;

#pragma unroll
            for (int ks = 0; ks < 8; ks++) {
                uint32_t ah[4], al[4];
                ldm_x4(ah, sb + aoff + ks * 32);
                ldm_x4(al, sb + AQ_BYTES + aoff + ks * 32);
#pragma unroll
                for (int ntl = 0; ntl < 4; ntl++) {
                    uint32_t bh[4], bl[4];
                    uint32_t bo = boff_n + (uint32_t)(ntl * 16) * TSTR_B + ks * 32;
                    ldm_x4(bh, KHO + bo);
                    ldm_x4(bl, KLO + bo);
                    mma_bf16(sacc[2 * ntl], ah, bh);
                    mma_bf16(sacc[2 * ntl], ah, bl);
                    mma_bf16(sacc[2 * ntl], al, bh);
                    mma_bf16(sacc[2 * ntl + 1], ah, bh + 2);
                    mma_bf16(sacc[2 * ntl + 1], ah, bl + 2);
                    mma_bf16(sacc[2 * ntl + 1], al, bh + 2);
                }
            }

            // ---- ALiBi + mask (fast path for fully-valid tiles) ----
            const bool allvalid = (kt + 63 <= wq_lo) && (kt >= wq_hi - WINDOW);
            if (allvalid) {
                const float f0 = slope2 * (float)(qr0 - kt - ((lane & 3) << 1));
                const float f1 = f0 - slope2;
                const float f2 = f0 + 8.0f * slope2;
                const float f3 = f2 - slope2;
#pragma unroll
                for (int t = 0; t < 8; t++) {
                    const float dt = (float)(8 * t) * slope2;
                    sacc[t][0] += f0 - dt;
                    sacc[t][1] += f1 - dt;
                    sacc[t][2] += f2 - dt;
                    sacc[t][3] += f3 - dt;
                }
            } else {
#pragma unroll
                for (int t = 0; t < 8; t++) {
                    int c0 = kt + t * 8 + ((lane & 3) << 1);
                    int c1 = c0 + 1;
                    int d00 = qr0 - c0, d01 = qr0 - c1, d10 = qr1 - c0, d11 = qr1 - c1;
                    sacc[t][0] = (d00 >= 0 && d00 <= WINDOW) ? sacc[t][0] + slope2 * (float)d00 : -1e32f;
                    sacc[t][1] = (d01 >= 0 && d01 <= WINDOW) ? sacc[t][1] + slope2 * (float)d01 : -1e32f;
                    sacc[t][2] = (d10 >= 0 && d10 <= WINDOW) ? sacc[t][2] + slope2 * (float)d10 : -1e32f;
                    sacc[t][3] = (d11 >= 0 && d11 <= WINDOW) ? sacc[t][3] + slope2 * (float)d11 : -1e32f;
                }
            }

            float mx0 = -1e32f, mx1 = -1e32f;
#pragma unroll
            for (int t = 0; t < 8; t++) {
                mx0 = fmaxf(mx0, fmaxf(sacc[t][0], sacc[t][1]));
                mx1 = fmaxf(mx1, fmaxf(sacc[t][2], sacc[t][3]));
            }
            mx0 = fmaxf(mx0, __shfl_xor_sync(0xffffffffu, mx0, 1));
            mx0 = fmaxf(mx0, __shfl_xor_sync(0xffffffffu, mx0, 2));
            mx1 = fmaxf(mx1, __shfl_xor_sync(0xffffffffu, mx1, 1));
            mx1 = fmaxf(mx1, __shfl_xor_sync(0xffffffffu, mx1, 2));
            float mn0 = fmaxf(m0r, mx0), mn1 = fmaxf(m1r, mx1);
            // warp-vote: skipping the rescale is exact when no lane's max moved
            const bool nochg = (mn0 == m0r) && (mn1 == m1r);
            const bool allsame = __all_sync(0xffffffffu, nochg);

            float ps0 = 0.0f, ps1 = 0.0f;
#pragma unroll
            for (int t = 0; t < 8; t++) {
                sacc[t][0] = ex2(sacc[t][0] - mn0);
                sacc[t][1] = ex2(sacc[t][1] - mn0);
                sacc[t][2] = ex2(sacc[t][2] - mn1);
                sacc[t][3] = ex2(sacc[t][3] - mn1);
                ps0 += sacc[t][0] + sacc[t][1];
                ps1 += sacc[t][2] + sacc[t][3];
            }
            if (allsame) {
                l0 += ps0;
                l1 += ps1;
            } else {
                float a0 = ex2(m0r - mn0), a1 = ex2(m1r - mn1);
                l0 = l0 * a0 + ps0;
                l1 = l1 * a1 + ps1;
#pragma unroll
                for (int t = 0; t < 16; t++) {
                    oacc[t][0] *= a0; oacc[t][1] *= a0;
                    oacc[t][2] *= a1; oacc[t][3] *= a1;
                }
            }
            m0r = mn0; m1r = mn1;

            // ---- O += P V (no per-kp control flow) ----
#pragma unroll
            for (int kp = 0; kp < 4; kp++) {
                const float* s0 = sacc[2 * kp];
                const float* s1 = sacc[2 * kp + 1];
                uint32_t aPh[4], aPl[4];
                aPh[0] = __byte_perm(__float_as_uint(s0[0]), __float_as_uint(s0[1]), 0x7632);
                aPh[1] = __byte_perm(__float_as_uint(s0[2]), __float_as_uint(s0[3]), 0x7632);
                aPh[2] = __byte_perm(__float_as_uint(s1[0]), __float_as_uint(s1[1]), 0x7632);
                aPh[3] = __byte_perm(__float_as_uint(s1[2]), __float_as_uint(s1[3]), 0x7632);
                aPl[0] = pkbf(s0[0] - btrunc(s0[0]), s0[1] - btrunc(s0[1]));
                aPl[1] = pkbf(s0[2] - btrunc(s0[2]), s0[3] - btrunc(s0[3]));
                aPl[2] = pkbf(s1[0] - btrunc(s1[0]), s1[1] - btrunc(s1[1]));
                aPl[3] = pkbf(s1[2] - btrunc(s1[2]), s1[3] - btrunc(s1[3]));

                uint32_t vbase = voff_r + (uint32_t)(kp * 16) * TSTR_B;
#pragma unroll
                for (int nv = 0; nv < 8; nv++) {
                    uint32_t bvh[4], bvl[4];
                    uint32_t vo = vbase + nv * 32;
                    ldm_x4t(bvh, VHO + vo);
                    ldm_x4t(bvl, VLO + vo);
                    mma_bf16(oacc[2 * nv], aPh, bvh);
                    mma_bf16(oacc[2 * nv], aPh, bvl);
                    mma_bf16(oacc[2 * nv], aPl, bvh);
                    mma_bf16(oacc[2 * nv + 1], aPh, bvh + 2);
                    mma_bf16(oacc[2 * nv + 1], aPh, bvl + 2);
                    mma_bf16(oacc[2 * nv + 1], aPl, bvh + 2);
                }
            }
        }

        // reload the single KV buffer for the next tile
        if (it + 1 < nt) {
            const int ktn = kt + 64;
            __syncthreads();
            const __nv_bfloat16* srcs[4] = { Khg, Klg, Vhg, Vlg };
            for (int idx = tid; idx < 4096; idx += 128) {
                int arr = idx >> 10, r = (idx >> 4) & 63, c = idx & 15;
                cp16(sb + AST_OFF + arr * KV_TILE_B + r * TSTR_B + c * 16,
                     (const char*)srcs[arr] + (long)(ktn + r) * 256 + c * 16);
            }
            cp_commit();
            cp_wait<0>();
            __syncthreads();
        }
    }

    l0 += __shfl_xor_sync(0xffffffffu, l0, 1);
    l0 += __shfl_xor_sync(0xffffffffu, l0, 2);
    l1 += __shfl_xor_sync(0xffffffffu, l1, 1);
    l1 += __shfl_xor_sync(0xffffffffu, l1, 2);
    const float i0 = 1.0f / l0, i1 = 1.0f / l1;

    long r0 = ((long)b * SEQ + qr0) * (QH * DIM) + h * DIM + ((lane & 3) << 1);
    long r1 = ((long)b * SEQ + qr1) * (QH * DIM) + h * DIM + ((lane & 3) << 1);
#pragma unroll
    for (int t = 0; t < 16; t++) {
        uint32_t hp, lp;
        split2(oacc[t][0] * i0, oacc[t][1] * i0, hp, lp);
        *(uint32_t*)(g_Ah + r0 + t * 8) = hp;
        *(uint32_t*)(g_Al + r0 + t * 8) = lp;
        split2(oacc[t][2] * i1, oacc[t][3] * i1, hp, lp);
        *(uint32_t*)(g_Ah + r1 + t * 8) = hp;
        *(uint32_t*)(g_Al + r1 + t * 8) = lp;
    }
}

// ---------------------------------------------------------------------------
// Kernel C: proj split-K=8 partials. Single-buffered, 4 CTAs/SM.
// ---------------------------------------------------------------------------
#define ASTR_B 144
#define PA_TILE (64 * ASTR_B)
#define PW_TILE (64 * TSTR_B)
#define PSTAGE (2 * PA_TILE + 2 * PW_TILE)   // 53248
#define PROJ_SMEM PSTAGE
#define KSPLIT 8

__global__ void __launch_bounds__(128) proj_partial_kernel() {
    extern __shared__ char smc[];
    const uint32_t sb = smem_u32(smc);
    const int tid = threadIdx.x;
    const int lane = tid & 31;
    const int w = tid >> 5;
    const int m0w = w * 16;
    const int m0 = blockIdx.x * 64;
    const int ksplit = blockIdx.y;
    const int kbase = ksplit * (2048 / KSPLIT);

    auto load_chunk = [&](int k0) {
        for (int idx = tid; idx < 3072; idx += 128) {
            if (idx < 1024) {
                int arr = idx >> 9, r = (idx >> 3) & 63, c = idx & 7;
                const char* src = (const char*)(arr ? g_Al : g_Ah) +
                                  (long)(m0 + r) * 4096 + k0 * 2 + c * 16;
                cp16(sb + arr * PA_TILE + r * ASTR_B + c * 16, src);
            } else {
                int j = idx - 1024;
                int arr = j >> 10, r = (j >> 4) & 63, c = j & 15;
                const char* src = (const char*)(arr ? g_Wpl : g_Wph) +
                                  (long)(k0 + r) * 256 + c * 16;
                cp16(sb + 2 * PA_TILE + arr * PW_TILE + r * TSTR_B + c * 16, src);
            }
        }
    };

    const uint32_t aoffA = (uint32_t)(m0w + (lane & 15)) * ASTR_B + ((lane >> 4) << 3) * 2;
    const uint32_t voffW = (uint32_t)((lane & 8) + (lane & 7)) * TSTR_B + ((lane >> 4) << 3) * 2;

    float acc[16][4];
#pragma unroll
    for (int t = 0; t < 16; t++)
#pragma unroll
        for (int j = 0; j < 4; j++) acc[t][j] = 0.0f;

    for (int it = 0; it < 2048 / KSPLIT / 64; it++) {
        load_chunk(kbase + it * 64);
        cp_commit();
        cp_wait<0>();
        __syncthreads();

        const uint32_t AH = sb, AL = sb + PA_TILE;
        const uint32_t WH = sb + 2 * PA_TILE, WL = WH + PW_TILE;

#pragma unroll
        for (int ks = 0; ks < 4; ks++) {
            uint32_t ah[4], al[4];
            ldm_x4(ah, AH + aoffA + ks * 32);
            ldm_x4(al, AL + aoffA + ks * 32);
            uint32_t vbase = voffW + (uint32_t)(ks * 16) * TSTR_B;
#pragma unroll
            for (int nv = 0; nv < 8; nv++) {
                uint32_t bh[4], bl[4];
                ldm_x4t(bh, WH + vbase + nv * 32);
                ldm_x4t(bl, WL + vbase + nv * 32);
                mma_bf16(acc[2 * nv], ah, bh);
                mma_bf16(acc[2 * nv], ah, bl);
                mma_bf16(acc[2 * nv], al, bh);
                mma_bf16(acc[2 * nv + 1], ah, bh + 2);
                mma_bf16(acc[2 * nv + 1], ah, bl + 2);
                mma_bf16(acc[2 * nv + 1], al, bh + 2);
            }
        }
        __syncthreads();
    }

    float* P = g_Pp + (long)ksplit * (BATCH * SEQ * DIM);
    const int mr0 = m0 + m0w + (lane >> 2);
#pragma unroll
    for (int t = 0; t < 16; t++) {
        int col = t * 8 + ((lane & 3) << 1);
        *(float2*)(P + (long)mr0 * 128 + col) = make_float2(acc[t][0], acc[t][1]);
        *(float2*)(P + (long)(mr0 + 8) * 128 + col) = make_float2(acc[t][2], acc[t][3]);
    }
}

// ---------------------------------------------------------------------------
// Kernel D: reduce 8 partials -> out (fixed order, deterministic)
// ---------------------------------------------------------------------------
#define NOUT4 (BATCH * SEQ * DIM / 4)
__global__ void __launch_bounds__(256) proj_reduce_kernel(float* __restrict__ out) {
    int i = blockIdx.x * 256 + threadIdx.x;
    if (i >= NOUT4) return;
    const long stride = (long)BATCH * SEQ * DIM;
    float4 r = *(const float4*)(g_Pp + 4 * (long)i);
#pragma unroll
    for (int s = 1; s < KSPLIT; s++) {
        float4 v = *(const float4*)(g_Pp + s * stride + 4 * (long)i);
        r.x += v.x; r.y += v.y; r.z += v.z; r.w += v.w;
    }
    *(float4*)(out + 4 * (long)i) = r;
}

// ---------------------------------------------------------------------------
extern "C" void kernel_launch(void* const* d_in, const int* in_sizes, int n_in,
                              void* d_out, int out_size) {
    const float* x     = (const float*)d_in[0];
    const float* Wqkv  = (const float*)d_in[1];
    const float* Wproj = (const float*)d_in[2];
    float* out = (float*)d_out;

    prep_kernel<<<(NPX + NPQ + NPP + 255) / 256, 256>>>(x, Wqkv, Wproj);

    cudaFuncSetAttribute(qkv_kernel, cudaFuncAttributeMaxDynamicSharedMemorySize, QKV_SMEM);
    qkv_kernel<<<dim3(8192 / 64, 24), 128, QKV_SMEM>>>();

    cudaFuncSetAttribute(attn_kernel, cudaFuncAttributeMaxDynamicSharedMemorySize, ATTN_SMEM);
    attn_kernel<<<dim3(SEQ / 64, QH, BATCH), 128, ATTN_SMEM>>>();

    cudaFuncSetAttribute(proj_partial_kernel, cudaFuncAttributeMaxDynamicSharedMemorySize, PROJ_SMEM);
    proj_partial_kernel<<<dim3(8192 / 64, KSPLIT), 128, PROJ_SMEM>>>();

    proj_reduce_kernel<<<(NOUT4 + 255) / 256, 256>>>(out);
}